// round 12
// baseline (speedup 1.0000x reference)
#include <cuda_runtime.h>
#include <cuda_fp16.h>
#include <math.h>

#define B 4096
#define T 200
#define D 128
#define U 128

// ---------------- device scratch ----------------
__device__ __align__(128) float g_att[(size_t)T * B];                  // [t][b_orig]
__device__ __align__(128) unsigned g_xproj[(size_t)T * B * 192];       // [t][p_sorted][perm] half2
__device__ int g_perm[B];                                              // sorted DESCENDING by L

__device__ __forceinline__ float sigt(float x) {
    float t;
    asm("tanh.approx.f32 %0, %1;" : "=f"(t) : "f"(0.5f * x));
    return fmaf(0.5f, t, 0.5f);
}
__device__ __forceinline__ float2 sig2(float a, float b) {
    __half2 p = __floats2half2_rn(0.5f * a, 0.5f * b);
    unsigned pu = *(unsigned*)&p, r;
    asm("tanh.approx.f16x2 %0, %1;" : "=r"(r) : "r"(pu));
    float2 t = __half22float2(*(__half2*)&r);
    return make_float2(fmaf(0.5f, t.x, 0.5f), fmaf(0.5f, t.y, 0.5f));
}
__device__ __forceinline__ float tanha(float x) {
    float t;
    asm("tanh.approx.f32 %0, %1;" : "=f"(t) : "f"(x));
    return t;
}
__device__ __forceinline__ float dicef(float x, float alpha) {
    float p = sigt(x);
    return p * x + alpha * (1.0f - p) * x;
}
__device__ __forceinline__ unsigned packh2(float a, float b) {
    __half2 h = __floats2half2_rn(a, b);
    return *(unsigned*)&h;
}
__device__ __forceinline__ float2 unpackh2(unsigned u) {
    return __half22float2(*(__half2*)&u);
}
__device__ __forceinline__ void mma_f16(float c[4], const unsigned a[4], const unsigned b[2]) {
    asm("mma.sync.aligned.m16n8k16.row.col.f32.f16.f16.f32 "
        "{%0,%1,%2,%3}, {%4,%5,%6,%7}, {%8,%9}, {%0,%1,%2,%3};\n"
        : "+f"(c[0]), "+f"(c[1]), "+f"(c[2]), "+f"(c[3])
        : "r"(a[0]), "r"(a[1]), "r"(a[2]), "r"(a[3]), "r"(b[0]), "r"(b[1]));
}
__device__ __forceinline__ void ldsm_x4(unsigned r[4], unsigned saddr) {
    asm volatile("ldmatrix.sync.aligned.m8n8.x4.shared.b16 {%0,%1,%2,%3}, [%4];"
        : "=r"(r[0]), "=r"(r[1]), "=r"(r[2]), "=r"(r[3]) : "r"(saddr));
}

// ---------------- counting sort (DESCENDING by L) ----------------
__global__ __launch_bounds__(512) void k_sort(const int* __restrict__ slen) {
    __shared__ int cnt[256];
    __shared__ int off[256];
    int tid = threadIdx.x;
    if (tid < 256) cnt[tid] = 0;
    __syncthreads();
    for (int b = tid; b < B; b += 512) {
        int L = slen[b]; L = min(max(L, 0), T);
        atomicAdd(&cnt[L], 1);
    }
    __syncthreads();
    if (tid == 0) {
        int acc = 0;
        for (int i = T; i >= 0; i--) { off[i] = acc; acc += cnt[i]; }
    }
    __syncthreads();
    for (int b = tid; b < B; b += 512) {
        int L = slen[b]; L = min(max(L, 0), T);
        int pos = atomicAdd(&off[L], 1);
        g_perm[pos] = b;
    }
}

// ---------------- fused attention + x-projection (R9 256-thread version) ----------------
__global__ __launch_bounds__(256) void k_fused(
    const float* __restrict__ x, const float* __restrict__ q_all,
    const int* __restrict__ slen,
    const float* __restrict__ W1, const float* __restrict__ a1,
    const float* __restrict__ W2, const float* __restrict__ a2,
    const float* __restrict__ W3,
    const float* __restrict__ Wu, const float* __restrict__ Wr, const float* __restrict__ Wc)
{
    extern __shared__ unsigned smw[];     // 24576 words: weight staging, then reuse
    unsigned* WtB  = smw;                 // 4096
    unsigned* xk   = smw + 4096;          // 2048
    unsigned* xout = smw + 6144;          // 6272 (rows of 196, 192 used)
    unsigned* h1h  = smw + 12416;         // 1024
    __shared__ unsigned W2h[16 * 32];
    __shared__ float a1s[64], a2s[16], W3s[16];
    __shared__ float qs[D], qproj[64];

    int tid = threadIdx.x;
    if (tid < 64) a1s[tid] = a1[tid];
    if (tid < 16) { a2s[tid] = a2[tid]; W3s[tid] = W3[tid]; }
    for (int e = tid; e < 512; e += 256) {
        int n = e & 15, kw = e >> 4;
        W2h[n * 32 + (kw ^ ((n & 7) << 2))] = packh2(W2[(2 * kw) * 16 + n], W2[(2 * kw + 1) * 16 + n]);
    }
    {
        const float* srcs[3] = { Wu, Wr, Wc };
        #pragma unroll
        for (int m = 0; m < 3; m++) {
            const float* S = srcs[m];
            unsigned* Wd = smw + m * 8192;
            for (int e = tid; e < 8192; e += 256) {
                int n = e & 127, kw = e >> 7;
                Wd[n * 64 + (kw ^ ((n & 7) << 2))] = packh2(S[(2 * kw) * 128 + n], S[(2 * kw + 1) * 128 + n]);
            }
        }
    }
    __syncthreads();

    const int w = tid >> 5, lane = tid & 31, g = lane >> 2, tig = lane & 3;
    const int gsw = g << 2;
    const int sub = lane >> 3, r8 = lane & 7;
    const int hi = sub >> 1;
    const int rsel = (sub & 1) * 8 + r8;

    unsigned wb[6][8][2];
    #pragma unroll
    for (int nt = 0; nt < 6; nt++) {
        int col = w * 48 + nt * 8 + g;
        int nb = (col >> 7) * 8192 + (col & 127) * 64;
        #pragma unroll
        for (int s = 0; s < 8; s++) {
            int k0 = (s * 8 + tig) ^ gsw, k1 = (s * 8 + tig + 4) ^ gsw;
            wb[nt][s][0] = smw[nb + k0];
            wb[nt][s][1] = smw[nb + k1];
        }
    }
    unsigned w2b[2][4][2];
    #pragma unroll
    for (int nt = 0; nt < 2; nt++) {
        int nb2 = (nt * 8 + g) * 32;
        #pragma unroll
        for (int s = 0; s < 4; s++) {
            w2b[nt][s][0] = W2h[nb2 + ((s * 8 + tig) ^ gsw)];
            w2b[nt][s][1] = W2h[nb2 + ((s * 8 + tig + 4) ^ gsw)];
        }
    }
    // permuted xout col: reader layout c' = ((k>>3)*4+(k&3))*6 + gate*2 + ((k>>2)&1)
    int cperm[6];
    #pragma unroll
    for (int nt = 0; nt < 6; nt++) {
        int W = w * 24 + nt * 4 + tig;
        int gate = W >> 6, kk = W & 63;
        cperm[nt] = ((kk >> 3) * 4 + (kk & 3)) * 6 + gate * 2 + ((kk >> 2) & 1);
    }
    __syncthreads();   // staging region reusable

    unsigned h1sa = (unsigned)__cvta_generic_to_shared(h1h);
    const int r_st = tid >> 3, c_st = tid & 7;
    const int rs_st = (r_st & 7) << 2;

    for (int j = 0; j < 8; j++) {
        int p = blockIdx.x + j * 512;
        int b = g_perm[p];
        int L = slen[b]; L = min(max(L, 0), T);
        if (L == 0) continue;

        if (tid < D) qs[tid] = q_all[(size_t)b * D + tid];
        __syncthreads();

        for (int e = tid; e < 4096; e += 256) {
            int n = e & 63, kw = e >> 6;
            int d0 = 2 * kw, d1 = 2 * kw + 1;
            float v0 = W1[(128 + d0) * 64 + n] - W1[(256 + d0) * 64 + n] + qs[d0] * W1[(384 + d0) * 64 + n];
            float v1 = W1[(128 + d1) * 64 + n] - W1[(256 + d1) * 64 + n] + qs[d1] * W1[(384 + d1) * 64 + n];
            WtB[n * 64 + (kw ^ ((n & 7) << 2))] = packh2(v0, v1);
        }
        {
            int colq = tid >> 2, sq = tid & 3;
            float acc = 0.0f;
            int dbase = sq * 32;
            #pragma unroll 8
            for (int d = dbase; d < dbase + 32; d++)
                acc += qs[d] * (W1[d * 64 + colq] + W1[(256 + d) * 64 + colq]);
            acc += __shfl_xor_sync(0xffffffffu, acc, 1);
            acc += __shfl_xor_sync(0xffffffffu, acc, 2);
            if (sq == 0) qproj[colq] = acc;
        }

        float4 xa[4];
        if (r_st < L) {
            const float4* xp = (const float4*)&x[((size_t)b * T + r_st) * D + c_st * 16];
            #pragma unroll
            for (int q4 = 0; q4 < 4; q4++) xa[q4] = xp[q4];
        } else {
            #pragma unroll
            for (int q4 = 0; q4 < 4; q4++) xa[q4] = make_float4(0.f, 0.f, 0.f, 0.f);
        }
        __syncthreads();

        for (int t0 = 0; t0 < L; t0 += 32) {
            {
                unsigned wv[8];
                #pragma unroll
                for (int q4 = 0; q4 < 4; q4++) {
                    wv[q4 * 2 + 0] = packh2(xa[q4].x, xa[q4].y);
                    wv[q4 * 2 + 1] = packh2(xa[q4].z, xa[q4].w);
                }
                int blockbase = r_st * 64 + ((c_st * 8) ^ (rs_st & 24));
                int lo = rs_st & 4;
                *(uint4*)&xk[blockbase + lo]       = make_uint4(wv[0], wv[1], wv[2], wv[3]);
                *(uint4*)&xk[blockbase + (lo ^ 4)] = make_uint4(wv[4], wv[5], wv[6], wv[7]);
            }
            __syncthreads();   // xk ready

            {
                int tnx = t0 + 32 + r_st;
                if (tnx < L) {
                    const float4* xp = (const float4*)&x[((size_t)b * T + tnx) * D + c_st * 16];
                    #pragma unroll
                    for (int q4 = 0; q4 < 4; q4++) xa[q4] = xp[q4];
                } else {
                    #pragma unroll
                    for (int q4 = 0; q4 < 4; q4++) xa[q4] = make_float4(0.f, 0.f, 0.f, 0.f);
                }
            }

            // ---- pass 1: attention layer-1 ----
            {
                float acca[2][4];
                float p0 = qproj[w * 8 + 2 * tig], p1 = qproj[w * 8 + 2 * tig + 1];
                acca[0][0] = p0; acca[0][1] = p1; acca[0][2] = p0; acca[0][3] = p1;
                acca[1][0] = p0; acca[1][1] = p1; acca[1][2] = p0; acca[1][3] = p1;
                int nbatt = (w * 8 + g) * 64;
                #pragma unroll
                for (int s = 0; s < 8; s++) {
                    int k0 = (s * 8 + tig) ^ gsw, k1 = (s * 8 + tig + 4) ^ gsw;
                    unsigned a[2][4], bb[2];
                    #pragma unroll
                    for (int mt = 0; mt < 2; mt++) {
                        int r0 = mt * 16 + g;
                        a[mt][0] = xk[r0 * 64 + k0];
                        a[mt][1] = xk[(r0 + 8) * 64 + k0];
                        a[mt][2] = xk[r0 * 64 + k1];
                        a[mt][3] = xk[(r0 + 8) * 64 + k1];
                    }
                    bb[0] = WtB[nbatt + k0];
                    bb[1] = WtB[nbatt + k1];
                    mma_f16(acca[0], a[0], bb);
                    mma_f16(acca[1], a[1], bb);
                }
                int col = w * 8 + 2 * tig;
                float al0 = a1s[col], al1 = a1s[col + 1];
                int chsw = ((w ^ g) << 2) + tig;
                #pragma unroll
                for (int mt = 0; mt < 2; mt++) {
                    int r0 = mt * 16 + g;
                    h1h[r0 * 32 + chsw]       = packh2(dicef(acca[mt][0], al0), dicef(acca[mt][1], al1));
                    h1h[(r0 + 8) * 32 + chsw] = packh2(dicef(acca[mt][2], al0), dicef(acca[mt][3], al1));
                }
            }

            // ---- pass 2: x-projection -> xout (permuted) ----
            {
                float acc[2][6][4];
                #pragma unroll
                for (int mt = 0; mt < 2; mt++)
                    #pragma unroll
                    for (int nt = 0; nt < 6; nt++)
                        #pragma unroll
                        for (int k = 0; k < 4; k++) acc[mt][nt][k] = 0.0f;

                #pragma unroll
                for (int s = 0; s < 8; s++) {
                    int k0 = (s * 8 + tig) ^ gsw, k1 = (s * 8 + tig + 4) ^ gsw;
                    unsigned a[2][4];
                    #pragma unroll
                    for (int mt = 0; mt < 2; mt++) {
                        int r0 = mt * 16 + g;
                        a[mt][0] = xk[r0 * 64 + k0];
                        a[mt][1] = xk[(r0 + 8) * 64 + k0];
                        a[mt][2] = xk[r0 * 64 + k1];
                        a[mt][3] = xk[(r0 + 8) * 64 + k1];
                    }
                    #pragma unroll
                    for (int nt = 0; nt < 6; nt++) {
                        mma_f16(acc[0][nt], a[0], wb[nt][s]);
                        mma_f16(acc[1][nt], a[1], wb[nt][s]);
                    }
                }
                #pragma unroll
                for (int mt = 0; mt < 2; mt++)
                    #pragma unroll
                    for (int nt = 0; nt < 6; nt++) {
                        int cp = cperm[nt];
                        xout[(mt * 16 + g) * 196 + cp]     = packh2(acc[mt][nt][0], acc[mt][nt][1]);
                        xout[(mt * 16 + 8 + g) * 196 + cp] = packh2(acc[mt][nt][2], acc[mt][nt][3]);
                    }
            }
            __syncthreads();

            if (w < 2) {
                int m0 = w * 16;
                float acc2[2][4];
                #pragma unroll
                for (int nt = 0; nt < 2; nt++)
                    #pragma unroll
                    for (int k = 0; k < 4; k++) acc2[nt][k] = 0.0f;
                unsigned baseH = h1sa + (unsigned)((m0 + rsel) * 128);
                #pragma unroll
                for (int s = 0; s < 4; s++) {
                    unsigned av[4];
                    ldsm_x4(av, baseH + (unsigned)((((2 * s + hi) ^ r8) << 4)));
                    mma_f16(acc2[0], av, w2b[0][s]);
                    mma_f16(acc2[1], av, w2b[1][s]);
                }
                float v0 = 0.0f, v1 = 0.0f;
                #pragma unroll
                for (int nt = 0; nt < 2; nt++) {
                    int c0 = nt * 8 + 2 * tig;
                    float wa = W3s[c0], wb3 = W3s[c0 + 1];
                    float aa = a2s[c0], ab = a2s[c0 + 1];
                    v0 += dicef(acc2[nt][0], aa) * wa + dicef(acc2[nt][1], ab) * wb3;
                    v1 += dicef(acc2[nt][2], aa) * wa + dicef(acc2[nt][3], ab) * wb3;
                }
                v0 += __shfl_xor_sync(0xffffffffu, v0, 1);
                v0 += __shfl_xor_sync(0xffffffffu, v0, 2);
                v1 += __shfl_xor_sync(0xffffffffu, v1, 1);
                v1 += __shfl_xor_sync(0xffffffffu, v1, 2);
                if (tig == 0) {
                    int trow0 = t0 + m0 + g;
                    int trow1 = trow0 + 8;
                    if (trow0 < L) g_att[(size_t)trow0 * B + b] = sigt(v0);
                    if (trow1 < L) g_att[(size_t)trow1 * B + b] = sigt(v1);
                }
            } else {
                int idx = tid - 64;          // 0..191
                int r = idx / 6, c = idx % 6;
                int t = t0 + r;
                if (t < L) {
                    size_t gb = ((size_t)t * B + p) * 192;
                    #pragma unroll
                    for (int k = 0; k < 8; k++) {
                        uint4 v = *(uint4*)&xout[r * 196 + c * 4 + k * 24];
                        *(uint4*)&g_xproj[gb + c * 4 + k * 24] = v;
                    }
                }
            }
            __syncthreads();
        }
    }
}

// ---------------- AUGRU scan: 16 rows/block (M=16), 256 blocks, 8 warps ----------------
__global__ __launch_bounds__(256) void k_augru(
    const int* __restrict__ slen,
    const float* __restrict__ Wu, const float* __restrict__ Wr, const float* __restrict__ Wc,
    float* __restrict__ out)
{
    extern __shared__ unsigned smw[];
    unsigned* hT  = smw + 24576;   // 1024 words: 16 rows x 64
    unsigned* rhT = smw + 25600;   // 1024 words
    __shared__ int   Ls[16];
    __shared__ int   bis[16];
    __shared__ float atts[2][16];
    __shared__ int   LmaxS;

    int tid = threadIdx.x;

    for (int e = tid; e < 8192; e += 256) {
        int n = e & 127, kw = e >> 7;
        int sw = n * 64 + (kw ^ ((n & 7) << 2));
        smw[sw]         = packh2(Wu[16384 + (2 * kw) * 128 + n], Wu[16384 + (2 * kw + 1) * 128 + n]);
        smw[8192 + sw]  = packh2(Wr[16384 + (2 * kw) * 128 + n], Wr[16384 + (2 * kw + 1) * 128 + n]);
        smw[16384 + sw] = packh2(Wc[16384 + (2 * kw) * 128 + n], Wc[16384 + (2 * kw + 1) * 128 + n]);
    }
    for (int e = tid; e < 2048; e += 256) hT[e] = 0u;   // hT + rhT
    if (tid < 16) {
        int b = g_perm[blockIdx.x * 16 + tid];
        bis[tid] = b;
        int L = slen[b]; L = min(max(L, 0), T);
        Ls[tid] = L;
    }
    __syncthreads();
    if (tid == 0) { int m = 0; for (int i = 0; i < 16; i++) m = max(m, Ls[i]); LmaxS = m; }

    const int w = tid >> 5, lane = tid & 31, g = lane >> 2, tig = lane & 3;
    const int gsw = g << 2;
    const int n0w = w * 16;

    unsigned wu[2][8][2], wr[2][8][2], wc[2][8][2];
    #pragma unroll
    for (int nt = 0; nt < 2; nt++) {
        int nb = (n0w + nt * 8 + g) * 64;
        #pragma unroll
        for (int s = 0; s < 8; s++) {
            int k0 = (s * 8 + tig) ^ gsw, k1 = (s * 8 + tig + 4) ^ gsw;
            wu[nt][s][0] = smw[nb + k0];          wu[nt][s][1] = smw[nb + k1];
            wr[nt][s][0] = smw[8192 + nb + k0];   wr[nt][s][1] = smw[8192 + nb + k1];
            wc[nt][s][0] = smw[16384 + nb + k0];  wc[nt][s][1] = smw[16384 + nb + k1];
        }
    }
    __syncthreads();
    const int Lmax = LmaxS;
    const int p0 = blockIdx.x * 16;

    const int sub = lane >> 3, r8 = lane & 7;
    const int hi = sub >> 1;
    const int rsel = (sub & 1) * 8 + r8;     // row 0..15
    unsigned hTsa = (unsigned)__cvta_generic_to_shared(hT);
    unsigned baseA = hTsa + (unsigned)(rsel * 256);

    int stoff[2];
    #pragma unroll
    for (int nt = 0; nt < 2; nt++) stoff[nt] = (((w * 2 + nt) ^ g) << 2) + tig;

    int myL[2];
    #pragma unroll
    for (int half = 0; half < 2; half++) myL[half] = Ls[half * 8 + g];

    float hm[2][4];   // [nt][half*2+j]
    #pragma unroll
    for (int nt = 0; nt < 2; nt++)
        #pragma unroll
        for (int k = 0; k < 4; k++) hm[nt][k] = 0.0f;

    const int coff = (w * 4 + tig) * 6;

    // preload all-gate x-projections for t=0 and atts[0]
    unsigned xal[2][2][3];   // [half][nt][gate]
    {
        #pragma unroll
        for (int half = 0; half < 2; half++) {
            size_t rb = ((size_t)p0 + half * 8 + g) * 192 + coff;
            uint2 v0 = *(const uint2*)&g_xproj[rb];
            uint2 v1 = *(const uint2*)&g_xproj[rb + 2];
            uint2 v2 = *(const uint2*)&g_xproj[rb + 4];
            xal[half][0][0] = v0.x; xal[half][1][0] = v0.y;
            xal[half][0][1] = v1.x; xal[half][1][1] = v1.y;
            xal[half][0][2] = v2.x; xal[half][1][2] = v2.y;
        }
        if (tid < 16) atts[0][tid] = g_att[(size_t)0 * B + bis[tid]];
    }
    __syncthreads();

    for (int t = 0; t < Lmax; t++) {
        int cur = t & 1, nxt = cur ^ 1;
        int tn = min(t + 1, T - 1);

        unsigned xaln[2][2][3];
        {
            size_t tbn = (size_t)tn * B + p0;
            #pragma unroll
            for (int half = 0; half < 2; half++) {
                size_t rbn = (tbn + half * 8 + g) * 192 + coff;
                uint2 v0 = *(const uint2*)&g_xproj[rbn];
                uint2 v1 = *(const uint2*)&g_xproj[rbn + 2];
                uint2 v2 = *(const uint2*)&g_xproj[rbn + 4];
                xaln[half][0][0] = v0.x; xaln[half][1][0] = v0.y;
                xaln[half][0][1] = v1.x; xaln[half][1][1] = v1.y;
                xaln[half][0][2] = v2.x; xaln[half][1][2] = v2.y;
            }
        }
        float attn_v = 0.0f;
        if (tid < 16) attn_v = g_att[(size_t)tn * B + bis[tid]];

        // phase A: accU = h@Whu, accR = h@Whr
        float accU[2][4], accR[2][4];
        #pragma unroll
        for (int nt = 0; nt < 2; nt++)
            #pragma unroll
            for (int k = 0; k < 4; k++) { accU[nt][k] = 0.0f; accR[nt][k] = 0.0f; }

        #pragma unroll
        for (int s = 0; s < 8; s++) {
            unsigned choff = (unsigned)((((2 * s + hi) ^ r8) << 4));
            unsigned ah[4];
            ldsm_x4(ah, baseA + choff);
            #pragma unroll
            for (int nt = 0; nt < 2; nt++) {
                mma_f16(accU[nt], ah, wu[nt][s]);
                mma_f16(accR[nt], ah, wr[nt][s]);
            }
        }

        // gates; store r*h
        float uu[2][4];
        #pragma unroll
        for (int nt = 0; nt < 2; nt++)
            #pragma unroll
            for (int half = 0; half < 2; half++) {
                int row = half * 8 + g;
                float2 xu = unpackh2(xal[half][nt][0]);
                float2 xr = unpackh2(xal[half][nt][1]);
                float2 uv = sig2(accU[nt][half * 2 + 0] + xu.x, accU[nt][half * 2 + 1] + xu.y);
                float2 rv = sig2(accR[nt][half * 2 + 0] + xr.x, accR[nt][half * 2 + 1] + xr.y);
                uu[nt][half * 2 + 0] = uv.x;
                uu[nt][half * 2 + 1] = uv.y;
                rhT[row * 64 + stoff[nt]] =
                    packh2(rv.x * hm[nt][half * 2 + 0], rv.y * hm[nt][half * 2 + 1]);
            }
        if (tid < 16) atts[nxt][tid] = attn_v;
        __syncthreads();

        // phase B: accC = x@Wxc + (r*h)@Whc
        float accC[2][4];
        #pragma unroll
        for (int nt = 0; nt < 2; nt++)
            #pragma unroll
            for (int half = 0; half < 2; half++) {
                float2 xc = unpackh2(xal[half][nt][2]);
                accC[nt][half * 2 + 0] = xc.x;
                accC[nt][half * 2 + 1] = xc.y;
            }

        #pragma unroll
        for (int s = 0; s < 8; s++) {
            unsigned choff = (unsigned)((((2 * s + hi) ^ r8) << 4)) + 4096u;  // rhT = hT + 4096 B
            unsigned ar[4];
            ldsm_x4(ar, baseA + choff);
            #pragma unroll
            for (int nt = 0; nt < 2; nt++)
                mma_f16(accC[nt], ar, wc[nt][s]);
        }

        // h update + refresh hT
        #pragma unroll
        for (int nt = 0; nt < 2; nt++)
            #pragma unroll
            for (int half = 0; half < 2; half++) {
                int row = half * 8 + g;
                if (t < myL[half]) {
                    float a_att = atts[cur][row];
                    float c0 = tanha(accC[nt][half * 2 + 0]);
                    float c1 = tanha(accC[nt][half * 2 + 1]);
                    float ut0 = uu[nt][half * 2 + 0] * a_att;
                    float ut1 = uu[nt][half * 2 + 1] * a_att;
                    hm[nt][half * 2 + 0] += ut0 * (c0 - hm[nt][half * 2 + 0]);
                    hm[nt][half * 2 + 1] += ut1 * (c1 - hm[nt][half * 2 + 1]);
                }
                hT[row * 64 + stoff[nt]] =
                    packh2(hm[nt][half * 2 + 0], hm[nt][half * 2 + 1]);
            }
        __syncthreads();

        #pragma unroll
        for (int half = 0; half < 2; half++)
            #pragma unroll
            for (int nt = 0; nt < 2; nt++)
                #pragma unroll
                for (int gt = 0; gt < 3; gt++)
                    xal[half][nt][gt] = xaln[half][nt][gt];
    }

    #pragma unroll
    for (int nt = 0; nt < 2; nt++) {
        int col = n0w + nt * 8 + tig * 2;
        #pragma unroll
        for (int half = 0; half < 2; half++) {
            int row = half * 8 + g;
            size_t base = (size_t)bis[row] * U + col;
            out[base]     = hm[nt][half * 2 + 0];
            out[base + 1] = hm[nt][half * 2 + 1];
        }
    }
}

// ---------------- launch ----------------
extern "C" void kernel_launch(void* const* d_in, const int* in_sizes, int n_in,
                              void* d_out, int out_size)
{
    const float* x    = (const float*)d_in[0];
    const float* q    = (const float*)d_in[1];
    const int*   slen = (const int*)d_in[2];
    const float* W1   = (const float*)d_in[3];
    const float* a1   = (const float*)d_in[4];
    const float* W2   = (const float*)d_in[5];
    const float* a2   = (const float*)d_in[6];
    const float* W3   = (const float*)d_in[7];
    const float* Wu   = (const float*)d_in[8];
    const float* Wr   = (const float*)d_in[9];
    const float* Wc   = (const float*)d_in[10];
    float* out = (float*)d_out;

    const int FUSED_SMEM = 24576 * 4;     //  98,304 B
    const int AUGRU_SMEM = 26624 * 4;     // 106,496 B

    cudaFuncSetAttribute(k_fused, cudaFuncAttributeMaxDynamicSharedMemorySize, FUSED_SMEM);
    cudaFuncSetAttribute(k_augru, cudaFuncAttributeMaxDynamicSharedMemorySize, AUGRU_SMEM);

    k_sort<<<1, 512>>>(slen);
    k_fused<<<512, 256, FUSED_SMEM>>>(x, q, slen, W1, a1, W2, a2, W3, Wu, Wr, Wc);
    k_augru<<<B / 16, 256, AUGRU_SMEM>>>(slen, Wu, Wr, Wc, out);
}

// round 13
// speedup vs baseline: 1.1375x; 1.1375x over previous
#include <cuda_runtime.h>
#include <cuda_fp16.h>
#include <math.h>

#define B 4096
#define T 200
#define D 128
#define U 128

// ---------------- device scratch ----------------
__device__ __align__(128) float g_att[(size_t)T * B];                  // [t][b_orig]
__device__ __align__(128) unsigned g_xproj[(size_t)T * B * 192];       // [t][p_sorted][perm] half2
__device__ int g_perm[B];

__device__ __forceinline__ float sigt(float x) {
    float t;
    asm("tanh.approx.f32 %0, %1;" : "=f"(t) : "f"(0.5f * x));
    return fmaf(0.5f, t, 0.5f);
}
__device__ __forceinline__ float2 sig2(float a, float b) {
    __half2 p = __floats2half2_rn(0.5f * a, 0.5f * b);
    unsigned pu = *(unsigned*)&p, r;
    asm("tanh.approx.f16x2 %0, %1;" : "=r"(r) : "r"(pu));
    float2 t = __half22float2(*(__half2*)&r);
    return make_float2(fmaf(0.5f, t.x, 0.5f), fmaf(0.5f, t.y, 0.5f));
}
__device__ __forceinline__ float tanha(float x) {
    float t;
    asm("tanh.approx.f32 %0, %1;" : "=f"(t) : "f"(x));
    return t;
}
__device__ __forceinline__ float dicef(float x, float alpha) {
    float p = sigt(x);
    return p * x + alpha * (1.0f - p) * x;
}
__device__ __forceinline__ unsigned packh2(float a, float b) {
    __half2 h = __floats2half2_rn(a, b);
    return *(unsigned*)&h;
}
__device__ __forceinline__ float2 unpackh2(unsigned u) {
    return __half22float2(*(__half2*)&u);
}
__device__ __forceinline__ void mma_f16(float c[4], const unsigned a[4], const unsigned b[2]) {
    asm("mma.sync.aligned.m16n8k16.row.col.f32.f16.f16.f32 "
        "{%0,%1,%2,%3}, {%4,%5,%6,%7}, {%8,%9}, {%0,%1,%2,%3};\n"
        : "+f"(c[0]), "+f"(c[1]), "+f"(c[2]), "+f"(c[3])
        : "r"(a[0]), "r"(a[1]), "r"(a[2]), "r"(a[3]), "r"(b[0]), "r"(b[1]));
}
__device__ __forceinline__ void ldsm_x4(unsigned r[4], unsigned saddr) {
    asm volatile("ldmatrix.sync.aligned.m8n8.x4.shared.b16 {%0,%1,%2,%3}, [%4];"
        : "=r"(r[0]), "=r"(r[1]), "=r"(r[2]), "=r"(r[3]) : "r"(saddr));
}

// ---------------- counting sort (ascending, as R9) ----------------
__global__ __launch_bounds__(512) void k_sort(const int* __restrict__ slen) {
    __shared__ int cnt[256];
    __shared__ int off[256];
    int tid = threadIdx.x;
    if (tid < 256) cnt[tid] = 0;
    __syncthreads();
    for (int b = tid; b < B; b += 512) {
        int L = slen[b]; L = min(max(L, 0), T);
        atomicAdd(&cnt[L], 1);
    }
    __syncthreads();
    if (tid == 0) {
        int acc = 0;
        for (int i = 0; i <= T; i++) { off[i] = acc; acc += cnt[i]; }
    }
    __syncthreads();
    for (int b = tid; b < B; b += 512) {
        int L = slen[b]; L = min(max(L, 0), T);
        int pos = atomicAdd(&off[L], 1);
        g_perm[pos] = b;
    }
}

// ---------------- fused attention + x-projection: 1-barrier pipelined tiles ----------------
// smem words: weight staging 0..24575 (reused):
//   WtB @0 (4096), xk[2] @4096/@6144 (2048 each), xout[2] @8192/@14464 (6272 each),
//   h1h[2] @20736/@21760 (1024 each). total 22784 <= 24576.
__global__ __launch_bounds__(256) void k_fused(
    const float* __restrict__ x, const float* __restrict__ q_all,
    const int* __restrict__ slen,
    const float* __restrict__ W1, const float* __restrict__ a1,
    const float* __restrict__ W2, const float* __restrict__ a2,
    const float* __restrict__ W3,
    const float* __restrict__ Wu, const float* __restrict__ Wr, const float* __restrict__ Wc)
{
    extern __shared__ unsigned smw[];
    unsigned* WtB = smw;
    __shared__ unsigned W2h[16 * 32];
    __shared__ float a1s[64], a2s[16], W3s[16];
    __shared__ float qs[D], qproj[64];

    int tid = threadIdx.x;
    if (tid < 64) a1s[tid] = a1[tid];
    if (tid < 16) { a2s[tid] = a2[tid]; W3s[tid] = W3[tid]; }
    for (int e = tid; e < 512; e += 256) {
        int n = e & 15, kw = e >> 4;
        W2h[n * 32 + (kw ^ ((n & 7) << 2))] = packh2(W2[(2 * kw) * 16 + n], W2[(2 * kw + 1) * 16 + n]);
    }
    {
        const float* srcs[3] = { Wu, Wr, Wc };
        #pragma unroll
        for (int m = 0; m < 3; m++) {
            const float* S = srcs[m];
            unsigned* Wd = smw + m * 8192;
            for (int e = tid; e < 8192; e += 256) {
                int n = e & 127, kw = e >> 7;
                Wd[n * 64 + (kw ^ ((n & 7) << 2))] = packh2(S[(2 * kw) * 128 + n], S[(2 * kw + 1) * 128 + n]);
            }
        }
    }
    __syncthreads();

    const int w = tid >> 5, lane = tid & 31, g = lane >> 2, tig = lane & 3;
    const int gsw = g << 2;
    const int sub = lane >> 3, r8 = lane & 7;
    const int hi = sub >> 1;
    const int rsel = (sub & 1) * 8 + r8;

    // hoist xproj B-fragments: warp w -> cols w*48 .. w*48+47
    unsigned wb[6][8][2];
    #pragma unroll
    for (int nt = 0; nt < 6; nt++) {
        int col = w * 48 + nt * 8 + g;
        int nb = (col >> 7) * 8192 + (col & 127) * 64;
        #pragma unroll
        for (int s = 0; s < 8; s++) {
            int k0 = (s * 8 + tig) ^ gsw, k1 = (s * 8 + tig + 4) ^ gsw;
            wb[nt][s][0] = smw[nb + k0];
            wb[nt][s][1] = smw[nb + k1];
        }
    }
    unsigned w2b[2][4][2];
    #pragma unroll
    for (int nt = 0; nt < 2; nt++) {
        int nb2 = (nt * 8 + g) * 32;
        #pragma unroll
        for (int s = 0; s < 4; s++) {
            w2b[nt][s][0] = W2h[nb2 + ((s * 8 + tig) ^ gsw)];
            w2b[nt][s][1] = W2h[nb2 + ((s * 8 + tig + 4) ^ gsw)];
        }
    }
    int cperm[6];
    #pragma unroll
    for (int nt = 0; nt < 6; nt++) {
        int W = w * 24 + nt * 4 + tig;
        int gate = W >> 6, kk = W & 63;
        cperm[nt] = ((kk >> 3) * 4 + (kk & 3)) * 6 + gate * 2 + ((kk >> 2) & 1);
    }
    __syncthreads();   // staging region reusable

    unsigned* xkB[2]   = { smw + 4096,  smw + 6144 };
    unsigned* xoutB[2] = { smw + 8192,  smw + 14464 };
    unsigned* h1hB[2]  = { smw + 20736, smw + 21760 };
    unsigned xksa0  = (unsigned)__cvta_generic_to_shared(xkB[0]);
    unsigned h1sa0  = (unsigned)__cvta_generic_to_shared(h1hB[0]);

    const int r_st = tid >> 3, c_st = tid & 7;
    const int rs_st = (r_st & 7) << 2;
    const int st_blockbase = r_st * 64 + ((c_st * 8) ^ (rs_st & 24));
    const int st_lo = rs_st & 4;

    for (int j = 0; j < 8; j++) {
        int p = blockIdx.x + j * 512;
        int b = g_perm[p];
        int L = slen[b]; L = min(max(L, 0), T);
        if (L == 0) continue;

        if (tid < D) qs[tid] = q_all[(size_t)b * D + tid];
        __syncthreads();   // also protects WtB/h1h/xout from previous b's epilogue

        for (int e = tid; e < 4096; e += 256) {
            int n = e & 63, kw = e >> 6;
            int d0 = 2 * kw, d1 = 2 * kw + 1;
            float v0 = W1[(128 + d0) * 64 + n] - W1[(256 + d0) * 64 + n] + qs[d0] * W1[(384 + d0) * 64 + n];
            float v1 = W1[(128 + d1) * 64 + n] - W1[(256 + d1) * 64 + n] + qs[d1] * W1[(384 + d1) * 64 + n];
            WtB[n * 64 + (kw ^ ((n & 7) << 2))] = packh2(v0, v1);
        }
        {
            int colq = tid >> 2, sq = tid & 3;
            float acc = 0.0f;
            int dbase = sq * 32;
            #pragma unroll 8
            for (int d = dbase; d < dbase + 32; d++)
                acc += qs[d] * (W1[d * 64 + colq] + W1[(256 + d) * 64 + colq]);
            acc += __shfl_xor_sync(0xffffffffu, acc, 1);
            acc += __shfl_xor_sync(0xffffffffu, acc, 2);
            if (sq == 0) qproj[colq] = acc;
        }

        // prefetch tile 0
        float4 xa[4];
        if (r_st < L) {
            const float4* xp = (const float4*)&x[((size_t)b * T + r_st) * D + c_st * 16];
            #pragma unroll
            for (int q4 = 0; q4 < 4; q4++) xa[q4] = xp[q4];
        } else {
            #pragma unroll
            for (int q4 = 0; q4 < 4; q4++) xa[q4] = make_float4(0.f, 0.f, 0.f, 0.f);
        }
        __syncthreads();   // WtB + qproj ready

        // stage tile 0 -> xk[0]
        {
            unsigned wv[8];
            #pragma unroll
            for (int q4 = 0; q4 < 4; q4++) {
                wv[q4 * 2 + 0] = packh2(xa[q4].x, xa[q4].y);
                wv[q4 * 2 + 1] = packh2(xa[q4].z, xa[q4].w);
            }
            *(uint4*)&xkB[0][st_blockbase + st_lo]       = make_uint4(wv[0], wv[1], wv[2], wv[3]);
            *(uint4*)&xkB[0][st_blockbase + (st_lo ^ 4)] = make_uint4(wv[4], wv[5], wv[6], wv[7]);
        }
        // prefetch tile 1
        {
            int tnx = 32 + r_st;
            if (tnx < L) {
                const float4* xp = (const float4*)&x[((size_t)b * T + tnx) * D + c_st * 16];
                #pragma unroll
                for (int q4 = 0; q4 < 4; q4++) xa[q4] = xp[q4];
            } else {
                #pragma unroll
                for (int q4 = 0; q4 < 4; q4++) xa[q4] = make_float4(0.f, 0.f, 0.f, 0.f);
            }
        }
        __syncthreads();   // xk[0] ready

        int ntiles = (L + 31) >> 5;
        for (int i = 0; i < ntiles; i++) {
            int cur = i & 1, nxt = cur ^ 1;
            int t0 = i << 5;
            unsigned xksaC = xksa0 + (unsigned)(cur * 8192);
            unsigned baseXK0 = xksaC + (unsigned)(rsel * 256);
            unsigned baseXK1 = xksaC + (unsigned)((16 + rsel) * 256);
            unsigned* xoutC = xoutB[cur];
            unsigned* h1hC  = h1hB[cur];

            // ---- pass 1: attention layer-1 (ldsm A-frags) ----
            {
                float acca[2][4];
                float p0 = qproj[w * 8 + 2 * tig], p1 = qproj[w * 8 + 2 * tig + 1];
                acca[0][0] = p0; acca[0][1] = p1; acca[0][2] = p0; acca[0][3] = p1;
                acca[1][0] = p0; acca[1][1] = p1; acca[1][2] = p0; acca[1][3] = p1;
                int nbatt = (w * 8 + g) * 64;
                #pragma unroll
                for (int s = 0; s < 8; s++) {
                    unsigned choff = (unsigned)((((2 * s + hi) ^ r8) << 4));
                    unsigned a0[4], a1v[4], bb[2];
                    ldsm_x4(a0, baseXK0 + choff);
                    ldsm_x4(a1v, baseXK1 + choff);
                    int k0 = (s * 8 + tig) ^ gsw, k1 = (s * 8 + tig + 4) ^ gsw;
                    bb[0] = WtB[nbatt + k0];
                    bb[1] = WtB[nbatt + k1];
                    mma_f16(acca[0], a0, bb);
                    mma_f16(acca[1], a1v, bb);
                }
                int col = w * 8 + 2 * tig;
                float al0 = a1s[col], al1 = a1s[col + 1];
                int chsw = ((w ^ g) << 2) + tig;
                #pragma unroll
                for (int mt = 0; mt < 2; mt++) {
                    int r0 = mt * 16 + g;
                    h1hC[r0 * 32 + chsw]       = packh2(dicef(acca[mt][0], al0), dicef(acca[mt][1], al1));
                    h1hC[(r0 + 8) * 32 + chsw] = packh2(dicef(acca[mt][2], al0), dicef(acca[mt][3], al1));
                }
            }

            // ---- pass 2: x-projection -> xout[cur] ----
            {
                float acc[2][6][4];
                #pragma unroll
                for (int mt = 0; mt < 2; mt++)
                    #pragma unroll
                    for (int nt = 0; nt < 6; nt++)
                        #pragma unroll
                        for (int k = 0; k < 4; k++) acc[mt][nt][k] = 0.0f;

                #pragma unroll
                for (int s = 0; s < 8; s++) {
                    unsigned choff = (unsigned)((((2 * s + hi) ^ r8) << 4));
                    unsigned a0[4], a1v[4];
                    ldsm_x4(a0, baseXK0 + choff);
                    ldsm_x4(a1v, baseXK1 + choff);
                    #pragma unroll
                    for (int nt = 0; nt < 6; nt++) {
                        mma_f16(acc[0][nt], a0, wb[nt][s]);
                        mma_f16(acc[1][nt], a1v, wb[nt][s]);
                    }
                }
                #pragma unroll
                for (int mt = 0; mt < 2; mt++)
                    #pragma unroll
                    for (int nt = 0; nt < 6; nt++) {
                        int cp = cperm[nt];
                        xoutC[(mt * 16 + g) * 196 + cp]     = packh2(acc[mt][nt][0], acc[mt][nt][1]);
                        xoutC[(mt * 16 + 8 + g) * 196 + cp] = packh2(acc[mt][nt][2], acc[mt][nt][3]);
                    }
            }

            // stage prefetched regs -> xk[nxt]; prefetch tile i+2
            {
                unsigned wv[8];
                #pragma unroll
                for (int q4 = 0; q4 < 4; q4++) {
                    wv[q4 * 2 + 0] = packh2(xa[q4].x, xa[q4].y);
                    wv[q4 * 2 + 1] = packh2(xa[q4].z, xa[q4].w);
                }
                *(uint4*)&xkB[nxt][st_blockbase + st_lo]       = make_uint4(wv[0], wv[1], wv[2], wv[3]);
                *(uint4*)&xkB[nxt][st_blockbase + (st_lo ^ 4)] = make_uint4(wv[4], wv[5], wv[6], wv[7]);
            }
            {
                int tnx = t0 + 64 + r_st;
                if (tnx < L) {
                    const float4* xp = (const float4*)&x[((size_t)b * T + tnx) * D + c_st * 16];
                    #pragma unroll
                    for (int q4 = 0; q4 < 4; q4++) xa[q4] = xp[q4];
                } else {
                    #pragma unroll
                    for (int q4 = 0; q4 < 4; q4++) xa[q4] = make_float4(0.f, 0.f, 0.f, 0.f);
                }
            }
            __syncthreads();   // the ONE barrier: h1h/xout[cur] + xk[nxt] ready

            // ---- epilogue (overlaps next tile's passes) ----
            if (w < 2) {
                int m0 = w * 16;
                float acc2[2][4];
                #pragma unroll
                for (int nt = 0; nt < 2; nt++)
                    #pragma unroll
                    for (int k = 0; k < 4; k++) acc2[nt][k] = 0.0f;
                unsigned baseH = h1sa0 + (unsigned)(cur * 4096) + (unsigned)((m0 + rsel) * 128);
                #pragma unroll
                for (int s = 0; s < 4; s++) {
                    unsigned av[4];
                    ldsm_x4(av, baseH + (unsigned)((((2 * s + hi) ^ r8) << 4)));
                    mma_f16(acc2[0], av, w2b[0][s]);
                    mma_f16(acc2[1], av, w2b[1][s]);
                }
                float v0 = 0.0f, v1 = 0.0f;
                #pragma unroll
                for (int nt = 0; nt < 2; nt++) {
                    int c0 = nt * 8 + 2 * tig;
                    float wa = W3s[c0], wb3 = W3s[c0 + 1];
                    float aa = a2s[c0], ab = a2s[c0 + 1];
                    v0 += dicef(acc2[nt][0], aa) * wa + dicef(acc2[nt][1], ab) * wb3;
                    v1 += dicef(acc2[nt][2], aa) * wa + dicef(acc2[nt][3], ab) * wb3;
                }
                v0 += __shfl_xor_sync(0xffffffffu, v0, 1);
                v0 += __shfl_xor_sync(0xffffffffu, v0, 2);
                v1 += __shfl_xor_sync(0xffffffffu, v1, 1);
                v1 += __shfl_xor_sync(0xffffffffu, v1, 2);
                if (tig == 0) {
                    int trow0 = t0 + m0 + g;
                    int trow1 = trow0 + 8;
                    if (trow0 < L) g_att[(size_t)trow0 * B + b] = sigt(v0);
                    if (trow1 < L) g_att[(size_t)trow1 * B + b] = sigt(v1);
                }
            } else {
                int idx = tid - 64;          // 0..191
                int r = idx / 6, c = idx % 6;
                int t = t0 + r;
                if (t < L) {
                    size_t gb = ((size_t)t * B + p) * 192;
                    #pragma unroll
                    for (int k = 0; k < 8; k++) {
                        uint4 v = *(uint4*)&xoutC[r * 196 + c * 4 + k * 24];
                        *(uint4*)&g_xproj[gb + c * 4 + k * 24] = v;
                    }
                }
            }
        }
    }
}

// ---------------- AUGRU scan (R9 8-warp, 32 rows, 128 blocks) ----------------
__global__ __launch_bounds__(256) void k_augru(
    const int* __restrict__ slen,
    const float* __restrict__ Wu, const float* __restrict__ Wr, const float* __restrict__ Wc,
    float* __restrict__ out)
{
    extern __shared__ unsigned smw[];
    unsigned* hT  = smw + 24576;
    unsigned* rhT = smw + 26624;
    __shared__ int   Ls[32];
    __shared__ int   bis[32];
    __shared__ float atts[2][32];
    __shared__ int   LmaxS;

    int tid = threadIdx.x;

    for (int e = tid; e < 8192; e += 256) {
        int n = e & 127, kw = e >> 7;
        int sw = n * 64 + (kw ^ ((n & 7) << 2));
        smw[sw]         = packh2(Wu[16384 + (2 * kw) * 128 + n], Wu[16384 + (2 * kw + 1) * 128 + n]);
        smw[8192 + sw]  = packh2(Wr[16384 + (2 * kw) * 128 + n], Wr[16384 + (2 * kw + 1) * 128 + n]);
        smw[16384 + sw] = packh2(Wc[16384 + (2 * kw) * 128 + n], Wc[16384 + (2 * kw + 1) * 128 + n]);
    }
    for (int e = tid; e < 4096; e += 256) hT[e] = 0u;
    if (tid < 32) {
        int b = g_perm[blockIdx.x * 32 + tid];
        bis[tid] = b;
        int L = slen[b]; L = min(max(L, 0), T);
        Ls[tid] = L;
    }
    __syncthreads();
    if (tid == 0) { int m = 0; for (int i = 0; i < 32; i++) m = max(m, Ls[i]); LmaxS = m; }

    const int w = tid >> 5, lane = tid & 31, g = lane >> 2, tig = lane & 3;
    const int gsw = g << 2;
    const int n0w = w * 16;

    unsigned wu[2][8][2], wr[2][8][2], wc[2][8][2];
    #pragma unroll
    for (int nt = 0; nt < 2; nt++) {
        int nb = (n0w + nt * 8 + g) * 64;
        #pragma unroll
        for (int s = 0; s < 8; s++) {
            int k0 = (s * 8 + tig) ^ gsw, k1 = (s * 8 + tig + 4) ^ gsw;
            wu[nt][s][0] = smw[nb + k0];          wu[nt][s][1] = smw[nb + k1];
            wr[nt][s][0] = smw[8192 + nb + k0];   wr[nt][s][1] = smw[8192 + nb + k1];
            wc[nt][s][0] = smw[16384 + nb + k0];  wc[nt][s][1] = smw[16384 + nb + k1];
        }
    }
    __syncthreads();
    const int Lmax = LmaxS;
    const int p0 = blockIdx.x * 32;

    const int sub = lane >> 3, r8 = lane & 7;
    const int hi = sub >> 1;
    const int rsel = (sub & 1) * 8 + r8;
    unsigned hTsa = (unsigned)__cvta_generic_to_shared(hT);
    unsigned baseA[2];
    baseA[0] = hTsa + (unsigned)(rsel * 256);
    baseA[1] = hTsa + (unsigned)((16 + rsel) * 256);

    int stoff[2];
    #pragma unroll
    for (int nt = 0; nt < 2; nt++) stoff[nt] = (((w * 2 + nt) ^ g) << 2) + tig;

    int myL[4];
    #pragma unroll
    for (int ri = 0; ri < 4; ri++) myL[ri] = Ls[(ri >> 1) * 16 + (ri & 1) * 8 + g];

    float hm[2][2][4];
    #pragma unroll
    for (int mt = 0; mt < 2; mt++)
        #pragma unroll
        for (int nt = 0; nt < 2; nt++)
            #pragma unroll
            for (int k = 0; k < 4; k++) hm[mt][nt][k] = 0.0f;

    const int coff = (w * 4 + tig) * 6;

    unsigned xal[2][2][2][3];
    {
        #pragma unroll
        for (int mt = 0; mt < 2; mt++)
            #pragma unroll
            for (int half = 0; half < 2; half++) {
                size_t rb = ((size_t)p0 + mt * 16 + half * 8 + g) * 192 + coff;
                uint2 v0 = *(const uint2*)&g_xproj[rb];
                uint2 v1 = *(const uint2*)&g_xproj[rb + 2];
                uint2 v2 = *(const uint2*)&g_xproj[rb + 4];
                xal[mt][half][0][0] = v0.x; xal[mt][half][1][0] = v0.y;
                xal[mt][half][0][1] = v1.x; xal[mt][half][1][1] = v1.y;
                xal[mt][half][0][2] = v2.x; xal[mt][half][1][2] = v2.y;
            }
        if (tid < 32) atts[0][tid] = g_att[(size_t)0 * B + bis[tid]];
    }
    __syncthreads();

    for (int t = 0; t < Lmax; t++) {
        int cur = t & 1, nxt = cur ^ 1;
        int tn = min(t + 1, T - 1);

        unsigned xaln[2][2][2][3];
        {
            size_t tbn = (size_t)tn * B + p0;
            #pragma unroll
            for (int mt = 0; mt < 2; mt++)
                #pragma unroll
                for (int half = 0; half < 2; half++) {
                    size_t rbn = (tbn + mt * 16 + half * 8 + g) * 192 + coff;
                    uint2 v0 = *(const uint2*)&g_xproj[rbn];
                    uint2 v1 = *(const uint2*)&g_xproj[rbn + 2];
                    uint2 v2 = *(const uint2*)&g_xproj[rbn + 4];
                    xaln[mt][half][0][0] = v0.x; xaln[mt][half][1][0] = v0.y;
                    xaln[mt][half][0][1] = v1.x; xaln[mt][half][1][1] = v1.y;
                    xaln[mt][half][0][2] = v2.x; xaln[mt][half][1][2] = v2.y;
                }
        }
        float attn_v = 0.0f;
        if (tid < 32) attn_v = g_att[(size_t)tn * B + bis[tid]];

        float accU[2][2][4], accR[2][2][4];
        #pragma unroll
        for (int mt = 0; mt < 2; mt++)
            #pragma unroll
            for (int nt = 0; nt < 2; nt++)
                #pragma unroll
                for (int k = 0; k < 4; k++) { accU[mt][nt][k] = 0.0f; accR[mt][nt][k] = 0.0f; }

        #pragma unroll
        for (int s = 0; s < 8; s++) {
            unsigned choff = (unsigned)((((2 * s + hi) ^ r8) << 4));
            unsigned ah[2][4];
            ldsm_x4(ah[0], baseA[0] + choff);
            ldsm_x4(ah[1], baseA[1] + choff);
            #pragma unroll
            for (int nt = 0; nt < 2; nt++)
                #pragma unroll
                for (int mt = 0; mt < 2; mt++) {
                    mma_f16(accU[mt][nt], ah[mt], wu[nt][s]);
                    mma_f16(accR[mt][nt], ah[mt], wr[nt][s]);
                }
        }

        float uu[2][2][4];
        #pragma unroll
        for (int mt = 0; mt < 2; mt++)
            #pragma unroll
            for (int nt = 0; nt < 2; nt++)
                #pragma unroll
                for (int half = 0; half < 2; half++) {
                    int row = mt * 16 + half * 8 + g;
                    float2 xu = unpackh2(xal[mt][half][nt][0]);
                    float2 xr = unpackh2(xal[mt][half][nt][1]);
                    float2 uv = sig2(accU[mt][nt][half * 2 + 0] + xu.x, accU[mt][nt][half * 2 + 1] + xu.y);
                    float2 rv = sig2(accR[mt][nt][half * 2 + 0] + xr.x, accR[mt][nt][half * 2 + 1] + xr.y);
                    uu[mt][nt][half * 2 + 0] = uv.x;
                    uu[mt][nt][half * 2 + 1] = uv.y;
                    rhT[row * 64 + stoff[nt]] =
                        packh2(rv.x * hm[mt][nt][half * 2 + 0], rv.y * hm[mt][nt][half * 2 + 1]);
                }
        if (tid < 32) atts[nxt][tid] = attn_v;
        __syncthreads();

        float accC[2][2][4];
        #pragma unroll
        for (int mt = 0; mt < 2; mt++)
            #pragma unroll
            for (int nt = 0; nt < 2; nt++)
                #pragma unroll
                for (int half = 0; half < 2; half++) {
                    float2 xc = unpackh2(xal[mt][half][nt][2]);
                    accC[mt][nt][half * 2 + 0] = xc.x;
                    accC[mt][nt][half * 2 + 1] = xc.y;
                }

        #pragma unroll
        for (int s = 0; s < 8; s++) {
            unsigned choff = (unsigned)((((2 * s + hi) ^ r8) << 4)) + 8192u;
            unsigned ar[2][4];
            ldsm_x4(ar[0], baseA[0] + choff);
            ldsm_x4(ar[1], baseA[1] + choff);
            #pragma unroll
            for (int nt = 0; nt < 2; nt++)
                #pragma unroll
                for (int mt = 0; mt < 2; mt++)
                    mma_f16(accC[mt][nt], ar[mt], wc[nt][s]);
        }

        #pragma unroll
        for (int mt = 0; mt < 2; mt++)
            #pragma unroll
            for (int nt = 0; nt < 2; nt++)
                #pragma unroll
                for (int half = 0; half < 2; half++) {
                    int ri = mt * 2 + half;
                    int row = mt * 16 + half * 8 + g;
                    if (t < myL[ri]) {
                        float a_att = atts[cur][row];
                        float c0 = tanha(accC[mt][nt][half * 2 + 0]);
                        float c1 = tanha(accC[mt][nt][half * 2 + 1]);
                        float ut0 = uu[mt][nt][half * 2 + 0] * a_att;
                        float ut1 = uu[mt][nt][half * 2 + 1] * a_att;
                        hm[mt][nt][half * 2 + 0] += ut0 * (c0 - hm[mt][nt][half * 2 + 0]);
                        hm[mt][nt][half * 2 + 1] += ut1 * (c1 - hm[mt][nt][half * 2 + 1]);
                    }
                    hT[row * 64 + stoff[nt]] =
                        packh2(hm[mt][nt][half * 2 + 0], hm[mt][nt][half * 2 + 1]);
                }
        __syncthreads();

        #pragma unroll
        for (int mt = 0; mt < 2; mt++)
            #pragma unroll
            for (int half = 0; half < 2; half++)
                #pragma unroll
                for (int nt = 0; nt < 2; nt++)
                    #pragma unroll
                    for (int gt = 0; gt < 3; gt++)
                        xal[mt][half][nt][gt] = xaln[mt][half][nt][gt];
    }

    #pragma unroll
    for (int mt = 0; mt < 2; mt++)
        #pragma unroll
        for (int nt = 0; nt < 2; nt++) {
            int col = n0w + nt * 8 + tig * 2;
            #pragma unroll
            for (int half = 0; half < 2; half++) {
                int row = mt * 16 + half * 8 + g;
                size_t base = (size_t)bis[row] * U + col;
                out[base]     = hm[mt][nt][half * 2 + 0];
                out[base + 1] = hm[mt][nt][half * 2 + 1];
            }
        }
}

// ---------------- launch ----------------
extern "C" void kernel_launch(void* const* d_in, const int* in_sizes, int n_in,
                              void* d_out, int out_size)
{
    const float* x    = (const float*)d_in[0];
    const float* q    = (const float*)d_in[1];
    const int*   slen = (const int*)d_in[2];
    const float* W1   = (const float*)d_in[3];
    const float* a1   = (const float*)d_in[4];
    const float* W2   = (const float*)d_in[5];
    const float* a2   = (const float*)d_in[6];
    const float* W3   = (const float*)d_in[7];
    const float* Wu   = (const float*)d_in[8];
    const float* Wr   = (const float*)d_in[9];
    const float* Wc   = (const float*)d_in[10];
    float* out = (float*)d_out;

    const int FUSED_SMEM = 24576 * 4;
    const int AUGRU_SMEM = 28672 * 4;

    cudaFuncSetAttribute(k_fused, cudaFuncAttributeMaxDynamicSharedMemorySize, FUSED_SMEM);
    cudaFuncSetAttribute(k_augru, cudaFuncAttributeMaxDynamicSharedMemorySize, AUGRU_SMEM);

    k_sort<<<1, 512>>>(slen);
    k_fused<<<512, 256, FUSED_SMEM>>>(x, q, slen, W1, a1, W2, a2, W3, Wu, Wr, Wc);
    k_augru<<<B / 32, 256, AUGRU_SMEM>>>(slen, Wu, Wr, Wc, out);
}

// round 14
// speedup vs baseline: 1.1678x; 1.0266x over previous
#include <cuda_runtime.h>
#include <cuda_fp16.h>
#include <math.h>

#define B 4096
#define T 200
#define D 128
#define U 128

// ---------------- device scratch ----------------
__device__ __align__(128) float g_att[(size_t)T * B];                  // [t][b_orig]
__device__ __align__(128) unsigned g_xproj[(size_t)T * B * 192];       // [t][p_sorted][perm] half2
__device__ int g_perm[B];

__device__ __forceinline__ float sigt(float x) {
    float t;
    asm("tanh.approx.f32 %0, %1;" : "=f"(t) : "f"(0.5f * x));
    return fmaf(0.5f, t, 0.5f);
}
__device__ __forceinline__ float2 sig2(float a, float b) {
    __half2 p = __floats2half2_rn(0.5f * a, 0.5f * b);
    unsigned pu = *(unsigned*)&p, r;
    asm("tanh.approx.f16x2 %0, %1;" : "=r"(r) : "r"(pu));
    float2 t = __half22float2(*(__half2*)&r);
    return make_float2(fmaf(0.5f, t.x, 0.5f), fmaf(0.5f, t.y, 0.5f));
}
__device__ __forceinline__ float tanha(float x) {
    float t;
    asm("tanh.approx.f32 %0, %1;" : "=f"(t) : "f"(x));
    return t;
}
__device__ __forceinline__ float dicef(float x, float alpha) {
    float p = sigt(x);
    return p * x + alpha * (1.0f - p) * x;
}
__device__ __forceinline__ unsigned packh2(float a, float b) {
    __half2 h = __floats2half2_rn(a, b);
    return *(unsigned*)&h;
}
__device__ __forceinline__ float2 unpackh2(unsigned u) {
    return __half22float2(*(__half2*)&u);
}
__device__ __forceinline__ void mma_f16(float c[4], const unsigned a[4], const unsigned b[2]) {
    asm("mma.sync.aligned.m16n8k16.row.col.f32.f16.f16.f32 "
        "{%0,%1,%2,%3}, {%4,%5,%6,%7}, {%8,%9}, {%0,%1,%2,%3};\n"
        : "+f"(c[0]), "+f"(c[1]), "+f"(c[2]), "+f"(c[3])
        : "r"(a[0]), "r"(a[1]), "r"(a[2]), "r"(a[3]), "r"(b[0]), "r"(b[1]));
}
__device__ __forceinline__ void ldsm_x4(unsigned r[4], unsigned saddr) {
    asm volatile("ldmatrix.sync.aligned.m8n8.x4.shared.b16 {%0,%1,%2,%3}, [%4];"
        : "=r"(r[0]), "=r"(r[1]), "=r"(r[2]), "=r"(r[3]) : "r"(saddr));
}

// ---------------- counting sort (ascending) ----------------
__global__ __launch_bounds__(512) void k_sort(const int* __restrict__ slen) {
    __shared__ int cnt[256];
    __shared__ int off[256];
    int tid = threadIdx.x;
    if (tid < 256) cnt[tid] = 0;
    __syncthreads();
    for (int b = tid; b < B; b += 512) {
        int L = slen[b]; L = min(max(L, 0), T);
        atomicAdd(&cnt[L], 1);
    }
    __syncthreads();
    if (tid == 0) {
        int acc = 0;
        for (int i = 0; i <= T; i++) { off[i] = acc; acc += cnt[i]; }
    }
    __syncthreads();
    for (int b = tid; b < B; b += 512) {
        int L = slen[b]; L = min(max(L, 0), T);
        int pos = atomicAdd(&off[L], 1);
        g_perm[pos] = b;
    }
}

// ---------------- fused attention + x-projection (R9 version) ----------------
__global__ __launch_bounds__(256) void k_fused(
    const float* __restrict__ x, const float* __restrict__ q_all,
    const int* __restrict__ slen,
    const float* __restrict__ W1, const float* __restrict__ a1,
    const float* __restrict__ W2, const float* __restrict__ a2,
    const float* __restrict__ W3,
    const float* __restrict__ Wu, const float* __restrict__ Wr, const float* __restrict__ Wc)
{
    extern __shared__ unsigned smw[];
    unsigned* WtB  = smw;                 // 4096
    unsigned* xk   = smw + 4096;          // 2048
    unsigned* xout = smw + 6144;          // 6272
    unsigned* h1h  = smw + 12416;         // 1024
    __shared__ unsigned W2h[16 * 32];
    __shared__ float a1s[64], a2s[16], W3s[16];
    __shared__ float qs[D], qproj[64];

    int tid = threadIdx.x;
    if (tid < 64) a1s[tid] = a1[tid];
    if (tid < 16) { a2s[tid] = a2[tid]; W3s[tid] = W3[tid]; }
    for (int e = tid; e < 512; e += 256) {
        int n = e & 15, kw = e >> 4;
        W2h[n * 32 + (kw ^ ((n & 7) << 2))] = packh2(W2[(2 * kw) * 16 + n], W2[(2 * kw + 1) * 16 + n]);
    }
    {
        const float* srcs[3] = { Wu, Wr, Wc };
        #pragma unroll
        for (int m = 0; m < 3; m++) {
            const float* S = srcs[m];
            unsigned* Wd = smw + m * 8192;
            for (int e = tid; e < 8192; e += 256) {
                int n = e & 127, kw = e >> 7;
                Wd[n * 64 + (kw ^ ((n & 7) << 2))] = packh2(S[(2 * kw) * 128 + n], S[(2 * kw + 1) * 128 + n]);
            }
        }
    }
    __syncthreads();

    const int w = tid >> 5, lane = tid & 31, g = lane >> 2, tig = lane & 3;
    const int gsw = g << 2;
    const int sub = lane >> 3, r8 = lane & 7;
    const int hi = sub >> 1;
    const int rsel = (sub & 1) * 8 + r8;

    unsigned wb[6][8][2];
    #pragma unroll
    for (int nt = 0; nt < 6; nt++) {
        int col = w * 48 + nt * 8 + g;
        int nb = (col >> 7) * 8192 + (col & 127) * 64;
        #pragma unroll
        for (int s = 0; s < 8; s++) {
            int k0 = (s * 8 + tig) ^ gsw, k1 = (s * 8 + tig + 4) ^ gsw;
            wb[nt][s][0] = smw[nb + k0];
            wb[nt][s][1] = smw[nb + k1];
        }
    }
    unsigned w2b[2][4][2];
    #pragma unroll
    for (int nt = 0; nt < 2; nt++) {
        int nb2 = (nt * 8 + g) * 32;
        #pragma unroll
        for (int s = 0; s < 4; s++) {
            w2b[nt][s][0] = W2h[nb2 + ((s * 8 + tig) ^ gsw)];
            w2b[nt][s][1] = W2h[nb2 + ((s * 8 + tig + 4) ^ gsw)];
        }
    }
    int cperm[6];
    #pragma unroll
    for (int nt = 0; nt < 6; nt++) {
        int W = w * 24 + nt * 4 + tig;
        int gate = W >> 6, kk = W & 63;
        cperm[nt] = ((kk >> 3) * 4 + (kk & 3)) * 6 + gate * 2 + ((kk >> 2) & 1);
    }
    __syncthreads();

    unsigned h1sa = (unsigned)__cvta_generic_to_shared(h1h);
    const int r_st = tid >> 3, c_st = tid & 7;
    const int rs_st = (r_st & 7) << 2;

    for (int j = 0; j < 8; j++) {
        int p = blockIdx.x + j * 512;
        int b = g_perm[p];
        int L = slen[b]; L = min(max(L, 0), T);
        if (L == 0) continue;

        if (tid < D) qs[tid] = q_all[(size_t)b * D + tid];
        __syncthreads();

        for (int e = tid; e < 4096; e += 256) {
            int n = e & 63, kw = e >> 6;
            int d0 = 2 * kw, d1 = 2 * kw + 1;
            float v0 = W1[(128 + d0) * 64 + n] - W1[(256 + d0) * 64 + n] + qs[d0] * W1[(384 + d0) * 64 + n];
            float v1 = W1[(128 + d1) * 64 + n] - W1[(256 + d1) * 64 + n] + qs[d1] * W1[(384 + d1) * 64 + n];
            WtB[n * 64 + (kw ^ ((n & 7) << 2))] = packh2(v0, v1);
        }
        {
            int colq = tid >> 2, sq = tid & 3;
            float acc = 0.0f;
            int dbase = sq * 32;
            #pragma unroll 8
            for (int d = dbase; d < dbase + 32; d++)
                acc += qs[d] * (W1[d * 64 + colq] + W1[(256 + d) * 64 + colq]);
            acc += __shfl_xor_sync(0xffffffffu, acc, 1);
            acc += __shfl_xor_sync(0xffffffffu, acc, 2);
            if (sq == 0) qproj[colq] = acc;
        }

        float4 xa[4];
        if (r_st < L) {
            const float4* xp = (const float4*)&x[((size_t)b * T + r_st) * D + c_st * 16];
            #pragma unroll
            for (int q4 = 0; q4 < 4; q4++) xa[q4] = xp[q4];
        } else {
            #pragma unroll
            for (int q4 = 0; q4 < 4; q4++) xa[q4] = make_float4(0.f, 0.f, 0.f, 0.f);
        }
        __syncthreads();

        for (int t0 = 0; t0 < L; t0 += 32) {
            {
                unsigned wv[8];
                #pragma unroll
                for (int q4 = 0; q4 < 4; q4++) {
                    wv[q4 * 2 + 0] = packh2(xa[q4].x, xa[q4].y);
                    wv[q4 * 2 + 1] = packh2(xa[q4].z, xa[q4].w);
                }
                int blockbase = r_st * 64 + ((c_st * 8) ^ (rs_st & 24));
                int lo = rs_st & 4;
                *(uint4*)&xk[blockbase + lo]       = make_uint4(wv[0], wv[1], wv[2], wv[3]);
                *(uint4*)&xk[blockbase + (lo ^ 4)] = make_uint4(wv[4], wv[5], wv[6], wv[7]);
            }
            __syncthreads();

            {
                int tnx = t0 + 32 + r_st;
                if (tnx < L) {
                    const float4* xp = (const float4*)&x[((size_t)b * T + tnx) * D + c_st * 16];
                    #pragma unroll
                    for (int q4 = 0; q4 < 4; q4++) xa[q4] = xp[q4];
                } else {
                    #pragma unroll
                    for (int q4 = 0; q4 < 4; q4++) xa[q4] = make_float4(0.f, 0.f, 0.f, 0.f);
                }
            }

            // pass 1: attention layer-1
            {
                float acca[2][4];
                float p0 = qproj[w * 8 + 2 * tig], p1 = qproj[w * 8 + 2 * tig + 1];
                acca[0][0] = p0; acca[0][1] = p1; acca[0][2] = p0; acca[0][3] = p1;
                acca[1][0] = p0; acca[1][1] = p1; acca[1][2] = p0; acca[1][3] = p1;
                int nbatt = (w * 8 + g) * 64;
                #pragma unroll
                for (int s = 0; s < 8; s++) {
                    int k0 = (s * 8 + tig) ^ gsw, k1 = (s * 8 + tig + 4) ^ gsw;
                    unsigned a[2][4], bb[2];
                    #pragma unroll
                    for (int mt = 0; mt < 2; mt++) {
                        int r0 = mt * 16 + g;
                        a[mt][0] = xk[r0 * 64 + k0];
                        a[mt][1] = xk[(r0 + 8) * 64 + k0];
                        a[mt][2] = xk[r0 * 64 + k1];
                        a[mt][3] = xk[(r0 + 8) * 64 + k1];
                    }
                    bb[0] = WtB[nbatt + k0];
                    bb[1] = WtB[nbatt + k1];
                    mma_f16(acca[0], a[0], bb);
                    mma_f16(acca[1], a[1], bb);
                }
                int col = w * 8 + 2 * tig;
                float al0 = a1s[col], al1 = a1s[col + 1];
                int chsw = ((w ^ g) << 2) + tig;
                #pragma unroll
                for (int mt = 0; mt < 2; mt++) {
                    int r0 = mt * 16 + g;
                    h1h[r0 * 32 + chsw]       = packh2(dicef(acca[mt][0], al0), dicef(acca[mt][1], al1));
                    h1h[(r0 + 8) * 32 + chsw] = packh2(dicef(acca[mt][2], al0), dicef(acca[mt][3], al1));
                }
            }

            // pass 2: x-projection -> xout (permuted)
            {
                float acc[2][6][4];
                #pragma unroll
                for (int mt = 0; mt < 2; mt++)
                    #pragma unroll
                    for (int nt = 0; nt < 6; nt++)
                        #pragma unroll
                        for (int k = 0; k < 4; k++) acc[mt][nt][k] = 0.0f;

                #pragma unroll
                for (int s = 0; s < 8; s++) {
                    int k0 = (s * 8 + tig) ^ gsw, k1 = (s * 8 + tig + 4) ^ gsw;
                    unsigned a[2][4];
                    #pragma unroll
                    for (int mt = 0; mt < 2; mt++) {
                        int r0 = mt * 16 + g;
                        a[mt][0] = xk[r0 * 64 + k0];
                        a[mt][1] = xk[(r0 + 8) * 64 + k0];
                        a[mt][2] = xk[r0 * 64 + k1];
                        a[mt][3] = xk[(r0 + 8) * 64 + k1];
                    }
                    #pragma unroll
                    for (int nt = 0; nt < 6; nt++) {
                        mma_f16(acc[0][nt], a[0], wb[nt][s]);
                        mma_f16(acc[1][nt], a[1], wb[nt][s]);
                    }
                }
                #pragma unroll
                for (int mt = 0; mt < 2; mt++)
                    #pragma unroll
                    for (int nt = 0; nt < 6; nt++) {
                        int cp = cperm[nt];
                        xout[(mt * 16 + g) * 196 + cp]     = packh2(acc[mt][nt][0], acc[mt][nt][1]);
                        xout[(mt * 16 + 8 + g) * 196 + cp] = packh2(acc[mt][nt][2], acc[mt][nt][3]);
                    }
            }
            __syncthreads();

            if (w < 2) {
                int m0 = w * 16;
                float acc2[2][4];
                #pragma unroll
                for (int nt = 0; nt < 2; nt++)
                    #pragma unroll
                    for (int k = 0; k < 4; k++) acc2[nt][k] = 0.0f;
                unsigned baseH = h1sa + (unsigned)((m0 + rsel) * 128);
                #pragma unroll
                for (int s = 0; s < 4; s++) {
                    unsigned av[4];
                    ldsm_x4(av, baseH + (unsigned)((((2 * s + hi) ^ r8) << 4)));
                    mma_f16(acc2[0], av, w2b[0][s]);
                    mma_f16(acc2[1], av, w2b[1][s]);
                }
                float v0 = 0.0f, v1 = 0.0f;
                #pragma unroll
                for (int nt = 0; nt < 2; nt++) {
                    int c0 = nt * 8 + 2 * tig;
                    float wa = W3s[c0], wb3 = W3s[c0 + 1];
                    float aa = a2s[c0], ab = a2s[c0 + 1];
                    v0 += dicef(acc2[nt][0], aa) * wa + dicef(acc2[nt][1], ab) * wb3;
                    v1 += dicef(acc2[nt][2], aa) * wa + dicef(acc2[nt][3], ab) * wb3;
                }
                v0 += __shfl_xor_sync(0xffffffffu, v0, 1);
                v0 += __shfl_xor_sync(0xffffffffu, v0, 2);
                v1 += __shfl_xor_sync(0xffffffffu, v1, 1);
                v1 += __shfl_xor_sync(0xffffffffu, v1, 2);
                if (tig == 0) {
                    int trow0 = t0 + m0 + g;
                    int trow1 = trow0 + 8;
                    if (trow0 < L) g_att[(size_t)trow0 * B + b] = sigt(v0);
                    if (trow1 < L) g_att[(size_t)trow1 * B + b] = sigt(v1);
                }
            } else {
                int idx = tid - 64;
                int r = idx / 6, c = idx % 6;
                int t = t0 + r;
                if (t < L) {
                    size_t gb = ((size_t)t * B + p) * 192;
                    #pragma unroll
                    for (int k = 0; k < 8; k++) {
                        uint4 v = *(uint4*)&xout[r * 196 + c * 4 + k * 24];
                        *(uint4*)&g_xproj[gb + c * 4 + k * 24] = v;
                    }
                }
            }
            __syncthreads();
        }
    }
}

// ---------------- AUGRU scan: M=16, 256 blocks, 2 blocks/SM, B-frags from smem ----------
// smem words: Whu 0, Whr 8192, Whc 16384, hT 24576 (1024), rhT 25600 (1024) = 26624 words
__global__ __launch_bounds__(256, 2) void k_augru(
    const int* __restrict__ slen,
    const float* __restrict__ Wu, const float* __restrict__ Wr, const float* __restrict__ Wc,
    float* __restrict__ out)
{
    extern __shared__ unsigned smw[];
    unsigned* hT  = smw + 24576;
    unsigned* rhT = smw + 25600;
    __shared__ int   Ls[16];
    __shared__ int   bis[16];
    __shared__ float atts[2][16];
    __shared__ int   LmaxS;

    int tid = threadIdx.x;

    for (int e = tid; e < 8192; e += 256) {
        int n = e & 127, kw = e >> 7;
        int sw = n * 64 + (kw ^ ((n & 7) << 2));
        smw[sw]         = packh2(Wu[16384 + (2 * kw) * 128 + n], Wu[16384 + (2 * kw + 1) * 128 + n]);
        smw[8192 + sw]  = packh2(Wr[16384 + (2 * kw) * 128 + n], Wr[16384 + (2 * kw + 1) * 128 + n]);
        smw[16384 + sw] = packh2(Wc[16384 + (2 * kw) * 128 + n], Wc[16384 + (2 * kw + 1) * 128 + n]);
    }
    for (int e = tid; e < 2048; e += 256) hT[e] = 0u;
    if (tid < 16) {
        int b = g_perm[blockIdx.x * 16 + tid];
        bis[tid] = b;
        int L = slen[b]; L = min(max(L, 0), T);
        Ls[tid] = L;
    }
    __syncthreads();
    if (tid == 0) { int m = 0; for (int i = 0; i < 16; i++) m = max(m, Ls[i]); LmaxS = m; }
    __syncthreads();
    const int Lmax = LmaxS;
    const int p0 = blockIdx.x * 16;

    const int w = tid >> 5, lane = tid & 31, g = lane >> 2, tig = lane & 3;
    const int gsw = g << 2;
    const int n0w = w * 16;

    const int sub = lane >> 3, r8 = lane & 7;
    const int hi = sub >> 1;
    const int rsel = (sub & 1) * 8 + r8;
    unsigned hTsa = (unsigned)__cvta_generic_to_shared(hT);
    unsigned baseA = hTsa + (unsigned)(rsel * 256);

    // B-frag smem word bases (per nt, per gate)
    int nb0 = (n0w + g) * 64;
    int nb1 = (n0w + 8 + g) * 64;

    int stoff[2];
    #pragma unroll
    for (int nt = 0; nt < 2; nt++) stoff[nt] = (((w * 2 + nt) ^ g) << 2) + tig;

    int myL[2];
    #pragma unroll
    for (int half = 0; half < 2; half++) myL[half] = Ls[half * 8 + g];

    float hm[2][4];
    #pragma unroll
    for (int nt = 0; nt < 2; nt++)
        #pragma unroll
        for (int k = 0; k < 4; k++) hm[nt][k] = 0.0f;

    const int coff = (w * 4 + tig) * 6;

    unsigned xal[2][2][3];   // [half][nt][gate]
    {
        #pragma unroll
        for (int half = 0; half < 2; half++) {
            size_t rb = ((size_t)p0 + half * 8 + g) * 192 + coff;
            uint2 v0 = *(const uint2*)&g_xproj[rb];
            uint2 v1 = *(const uint2*)&g_xproj[rb + 2];
            uint2 v2 = *(const uint2*)&g_xproj[rb + 4];
            xal[half][0][0] = v0.x; xal[half][1][0] = v0.y;
            xal[half][0][1] = v1.x; xal[half][1][1] = v1.y;
            xal[half][0][2] = v2.x; xal[half][1][2] = v2.y;
        }
        if (tid < 16) atts[0][tid] = g_att[(size_t)0 * B + bis[tid]];
    }
    __syncthreads();

    for (int t = 0; t < Lmax; t++) {
        int cur = t & 1, nxt = cur ^ 1;
        int tn = min(t + 1, T - 1);

        unsigned xaln[2][2][3];
        {
            size_t tbn = (size_t)tn * B + p0;
            #pragma unroll
            for (int half = 0; half < 2; half++) {
                size_t rbn = (tbn + half * 8 + g) * 192 + coff;
                uint2 v0 = *(const uint2*)&g_xproj[rbn];
                uint2 v1 = *(const uint2*)&g_xproj[rbn + 2];
                uint2 v2 = *(const uint2*)&g_xproj[rbn + 4];
                xaln[half][0][0] = v0.x; xaln[half][1][0] = v0.y;
                xaln[half][0][1] = v1.x; xaln[half][1][1] = v1.y;
                xaln[half][0][2] = v2.x; xaln[half][1][2] = v2.y;
            }
        }
        float attn_v = 0.0f;
        if (tid < 16) attn_v = g_att[(size_t)tn * B + bis[tid]];

        // phase A: accU = h@Whu, accR = h@Whr (B-frags streamed from smem)
        float accU[2][4], accR[2][4];
        #pragma unroll
        for (int nt = 0; nt < 2; nt++)
            #pragma unroll
            for (int k = 0; k < 4; k++) { accU[nt][k] = 0.0f; accR[nt][k] = 0.0f; }

        #pragma unroll
        for (int s = 0; s < 8; s++) {
            unsigned choff = (unsigned)((((2 * s + hi) ^ r8) << 4));
            unsigned ah[4];
            ldsm_x4(ah, baseA + choff);
            int k0 = (s * 8 + tig) ^ gsw, k1 = (s * 8 + tig + 4) ^ gsw;
            {
                unsigned bu[2] = { smw[nb0 + k0], smw[nb0 + k1] };
                unsigned br[2] = { smw[8192 + nb0 + k0], smw[8192 + nb0 + k1] };
                mma_f16(accU[0], ah, bu);
                mma_f16(accR[0], ah, br);
            }
            {
                unsigned bu[2] = { smw[nb1 + k0], smw[nb1 + k1] };
                unsigned br[2] = { smw[8192 + nb1 + k0], smw[8192 + nb1 + k1] };
                mma_f16(accU[1], ah, bu);
                mma_f16(accR[1], ah, br);
            }
        }

        // gates; store r*h
        float uu[2][4];
        #pragma unroll
        for (int nt = 0; nt < 2; nt++)
            #pragma unroll
            for (int half = 0; half < 2; half++) {
                int row = half * 8 + g;
                float2 xu = unpackh2(xal[half][nt][0]);
                float2 xr = unpackh2(xal[half][nt][1]);
                float2 uv = sig2(accU[nt][half * 2 + 0] + xu.x, accU[nt][half * 2 + 1] + xu.y);
                float2 rv = sig2(accR[nt][half * 2 + 0] + xr.x, accR[nt][half * 2 + 1] + xr.y);
                uu[nt][half * 2 + 0] = uv.x;
                uu[nt][half * 2 + 1] = uv.y;
                rhT[row * 64 + stoff[nt]] =
                    packh2(rv.x * hm[nt][half * 2 + 0], rv.y * hm[nt][half * 2 + 1]);
            }
        if (tid < 16) atts[nxt][tid] = attn_v;
        __syncthreads();

        // phase B: accC = x@Wxc + (r*h)@Whc
        float accC[2][4];
        #pragma unroll
        for (int nt = 0; nt < 2; nt++)
            #pragma unroll
            for (int half = 0; half < 2; half++) {
                float2 xc = unpackh2(xal[half][nt][2]);
                accC[nt][half * 2 + 0] = xc.x;
                accC[nt][half * 2 + 1] = xc.y;
            }

        #pragma unroll
        for (int s = 0; s < 8; s++) {
            unsigned choff = (unsigned)((((2 * s + hi) ^ r8) << 4)) + 4096u;  // rhT = hT + 4096 B
            unsigned ar[4];
            ldsm_x4(ar, baseA + choff);
            int k0 = (s * 8 + tig) ^ gsw, k1 = (s * 8 + tig + 4) ^ gsw;
            {
                unsigned bc[2] = { smw[16384 + nb0 + k0], smw[16384 + nb0 + k1] };
                mma_f16(accC[0], ar, bc);
            }
            {
                unsigned bc[2] = { smw[16384 + nb1 + k0], smw[16384 + nb1 + k1] };
                mma_f16(accC[1], ar, bc);
            }
        }

        // h update + refresh hT
        #pragma unroll
        for (int nt = 0; nt < 2; nt++)
            #pragma unroll
            for (int half = 0; half < 2; half++) {
                int row = half * 8 + g;
                if (t < myL[half]) {
                    float a_att = atts[cur][row];
                    float c0 = tanha(accC[nt][half * 2 + 0]);
                    float c1 = tanha(accC[nt][half * 2 + 1]);
                    float ut0 = uu[nt][half * 2 + 0] * a_att;
                    float ut1 = uu[nt][half * 2 + 1] * a_att;
                    hm[nt][half * 2 + 0] += ut0 * (c0 - hm[nt][half * 2 + 0]);
                    hm[nt][half * 2 + 1] += ut1 * (c1 - hm[nt][half * 2 + 1]);
                }
                hT[row * 64 + stoff[nt]] =
                    packh2(hm[nt][half * 2 + 0], hm[nt][half * 2 + 1]);
            }
        __syncthreads();

        #pragma unroll
        for (int half = 0; half < 2; half++)
            #pragma unroll
            for (int nt = 0; nt < 2; nt++)
                #pragma unroll
                for (int gt = 0; gt < 3; gt++)
                    xal[half][nt][gt] = xaln[half][nt][gt];
    }

    #pragma unroll
    for (int nt = 0; nt < 2; nt++) {
        int col = n0w + nt * 8 + tig * 2;
        #pragma unroll
        for (int half = 0; half < 2; half++) {
            int row = half * 8 + g;
            size_t base = (size_t)bis[row] * U + col;
            out[base]     = hm[nt][half * 2 + 0];
            out[base + 1] = hm[nt][half * 2 + 1];
        }
    }
}

// ---------------- launch ----------------
extern "C" void kernel_launch(void* const* d_in, const int* in_sizes, int n_in,
                              void* d_out, int out_size)
{
    const float* x    = (const float*)d_in[0];
    const float* q    = (const float*)d_in[1];
    const int*   slen = (const int*)d_in[2];
    const float* W1   = (const float*)d_in[3];
    const float* a1   = (const float*)d_in[4];
    const float* W2   = (const float*)d_in[5];
    const float* a2   = (const float*)d_in[6];
    const float* W3   = (const float*)d_in[7];
    const float* Wu   = (const float*)d_in[8];
    const float* Wr   = (const float*)d_in[9];
    const float* Wc   = (const float*)d_in[10];
    float* out = (float*)d_out;

    const int FUSED_SMEM = 24576 * 4;     //  98,304 B
    const int AUGRU_SMEM = 26624 * 4;     // 106,496 B  (x2 blocks/SM = 212,992 <= 227K)

    cudaFuncSetAttribute(k_fused, cudaFuncAttributeMaxDynamicSharedMemorySize, FUSED_SMEM);
    cudaFuncSetAttribute(k_augru, cudaFuncAttributeMaxDynamicSharedMemorySize, AUGRU_SMEM);

    k_sort<<<1, 512>>>(slen);
    k_fused<<<512, 256, FUSED_SMEM>>>(x, q, slen, W1, a1, W2, a2, W3, Wu, Wr, Wc);
    k_augru<<<B / 16, 256, AUGRU_SMEM>>>(slen, Wu, Wr, Wc, out);
}

// round 15
// speedup vs baseline: 1.1731x; 1.0046x over previous
#include <cuda_runtime.h>
#include <cuda_fp16.h>
#include <math.h>

#define B 4096
#define T 200
#define D 128
#define U 128

// ---------------- device scratch ----------------
__device__ __align__(128) float g_att[(size_t)T * B];                  // [t][b_orig]
__device__ __align__(128) unsigned g_xproj[(size_t)T * B * 192];       // [t][p_sorted][perm] half2
__device__ int g_perm[B];

__device__ __forceinline__ float sigt(float x) {
    float t;
    asm("tanh.approx.f32 %0, %1;" : "=f"(t) : "f"(0.5f * x));
    return fmaf(0.5f, t, 0.5f);
}
__device__ __forceinline__ float2 sig2(float a, float b) {
    __half2 p = __floats2half2_rn(0.5f * a, 0.5f * b);
    unsigned pu = *(unsigned*)&p, r;
    asm("tanh.approx.f16x2 %0, %1;" : "=r"(r) : "r"(pu));
    float2 t = __half22float2(*(__half2*)&r);
    return make_float2(fmaf(0.5f, t.x, 0.5f), fmaf(0.5f, t.y, 0.5f));
}
__device__ __forceinline__ float tanha(float x) {
    float t;
    asm("tanh.approx.f32 %0, %1;" : "=f"(t) : "f"(x));
    return t;
}
__device__ __forceinline__ float dicef(float x, float alpha) {
    float p = sigt(x);
    return p * x + alpha * (1.0f - p) * x;
}
__device__ __forceinline__ unsigned packh2(float a, float b) {
    __half2 h = __floats2half2_rn(a, b);
    return *(unsigned*)&h;
}
__device__ __forceinline__ float2 unpackh2(unsigned u) {
    return __half22float2(*(__half2*)&u);
}
__device__ __forceinline__ void mma_f16(float c[4], const unsigned a[4], const unsigned b[2]) {
    asm("mma.sync.aligned.m16n8k16.row.col.f32.f16.f16.f32 "
        "{%0,%1,%2,%3}, {%4,%5,%6,%7}, {%8,%9}, {%0,%1,%2,%3};\n"
        : "+f"(c[0]), "+f"(c[1]), "+f"(c[2]), "+f"(c[3])
        : "r"(a[0]), "r"(a[1]), "r"(a[2]), "r"(a[3]), "r"(b[0]), "r"(b[1]));
}
__device__ __forceinline__ void ldsm_x4(unsigned r[4], unsigned saddr) {
    asm volatile("ldmatrix.sync.aligned.m8n8.x4.shared.b16 {%0,%1,%2,%3}, [%4];"
        : "=r"(r[0]), "=r"(r[1]), "=r"(r[2]), "=r"(r[3]) : "r"(saddr));
}

// ---------------- counting sort (ascending) ----------------
__global__ __launch_bounds__(512) void k_sort(const int* __restrict__ slen) {
    __shared__ int cnt[256];
    __shared__ int off[256];
    int tid = threadIdx.x;
    if (tid < 256) cnt[tid] = 0;
    __syncthreads();
    for (int b = tid; b < B; b += 512) {
        int L = slen[b]; L = min(max(L, 0), T);
        atomicAdd(&cnt[L], 1);
    }
    __syncthreads();
    if (tid == 0) {
        int acc = 0;
        for (int i = 0; i <= T; i++) { off[i] = acc; acc += cnt[i]; }
    }
    __syncthreads();
    for (int b = tid; b < B; b += 512) {
        int L = slen[b]; L = min(max(L, 0), T);
        int pos = atomicAdd(&off[L], 1);
        g_perm[pos] = b;
    }
}

// ---------------- fused attention + x-projection: batch-PAIR tiles ----------------
// dyn smem words: weights staged 0..24575 (temp), then:
//   WtB0 @0 (4096), WtB1 @4096, xk0 @8192 (2048), xk1 @10240,
//   xout0 @12288 (6272), xout1 @18560, h1h0 @24832 (1024), h1h1 @25856. total 26880.
__global__ __launch_bounds__(256) void k_fused(
    const float* __restrict__ x, const float* __restrict__ q_all,
    const int* __restrict__ slen,
    const float* __restrict__ W1, const float* __restrict__ a1,
    const float* __restrict__ W2, const float* __restrict__ a2,
    const float* __restrict__ W3,
    const float* __restrict__ Wu, const float* __restrict__ Wr, const float* __restrict__ Wc)
{
    extern __shared__ unsigned smw[];
    __shared__ unsigned W2h[16 * 32];
    __shared__ float a1s[64], a2s[16], W3s[16];
    __shared__ float qs[D];
    __shared__ float qprojS[2][64];

    int tid = threadIdx.x;
    if (tid < 64) a1s[tid] = a1[tid];
    if (tid < 16) { a2s[tid] = a2[tid]; W3s[tid] = W3[tid]; }
    for (int e = tid; e < 512; e += 256) {
        int n = e & 15, kw = e >> 4;
        W2h[n * 32 + (kw ^ ((n & 7) << 2))] = packh2(W2[(2 * kw) * 16 + n], W2[(2 * kw + 1) * 16 + n]);
    }
    {
        const float* srcs[3] = { Wu, Wr, Wc };
        #pragma unroll
        for (int m = 0; m < 3; m++) {
            const float* S = srcs[m];
            unsigned* Wd = smw + m * 8192;
            for (int e = tid; e < 8192; e += 256) {
                int n = e & 127, kw = e >> 7;
                Wd[n * 64 + (kw ^ ((n & 7) << 2))] = packh2(S[(2 * kw) * 128 + n], S[(2 * kw + 1) * 128 + n]);
            }
        }
    }
    __syncthreads();

    const int w = tid >> 5, lane = tid & 31, g = lane >> 2, tig = lane & 3;
    const int gsw = g << 2;
    const int sub = lane >> 3, r8 = lane & 7;
    const int hi = sub >> 1;
    const int rsel = (sub & 1) * 8 + r8;

    // hoist xproj B-fragments
    unsigned wb[6][8][2];
    #pragma unroll
    for (int nt = 0; nt < 6; nt++) {
        int col = w * 48 + nt * 8 + g;
        int nb = (col >> 7) * 8192 + (col & 127) * 64;
        #pragma unroll
        for (int s = 0; s < 8; s++) {
            int k0 = (s * 8 + tig) ^ gsw, k1 = (s * 8 + tig + 4) ^ gsw;
            wb[nt][s][0] = smw[nb + k0];
            wb[nt][s][1] = smw[nb + k1];
        }
    }
    unsigned w2b[2][4][2];
    #pragma unroll
    for (int nt = 0; nt < 2; nt++) {
        int nb2 = (nt * 8 + g) * 32;
        #pragma unroll
        for (int s = 0; s < 4; s++) {
            w2b[nt][s][0] = W2h[nb2 + ((s * 8 + tig) ^ gsw)];
            w2b[nt][s][1] = W2h[nb2 + ((s * 8 + tig + 4) ^ gsw)];
        }
    }
    int cperm[6];
    #pragma unroll
    for (int nt = 0; nt < 6; nt++) {
        int W = w * 24 + nt * 4 + tig;
        int gate = W >> 6, kk = W & 63;
        cperm[nt] = ((kk >> 3) * 4 + (kk & 3)) * 6 + gate * 2 + ((kk >> 2) & 1);
    }
    __syncthreads();   // staging region reusable

    unsigned* WtBB[2]  = { smw,         smw + 4096 };
    unsigned* xkB[2]   = { smw + 8192,  smw + 10240 };
    unsigned* xoutB[2] = { smw + 12288, smw + 18560 };
    unsigned* h1hB[2]  = { smw + 24832, smw + 25856 };

    const int r_st = tid >> 3, c_st = tid & 7;
    const int rs_st = (r_st & 7) << 2;
    const int st_blockbase = r_st * 64 + ((c_st * 8) ^ (rs_st & 24));
    const int st_lo = rs_st & 4;

    for (int jj = 0; jj < 4; jj++) {
        int pp[2], bb2[2], LL[2];
        pp[0] = 2 * blockIdx.x + jj * 1024;
        pp[1] = pp[0] + 1;
        bb2[0] = g_perm[pp[0]]; bb2[1] = g_perm[pp[1]];
        LL[0] = min(max(slen[bb2[0]], 0), T);
        LL[1] = min(max(slen[bb2[1]], 0), T);
        int Lmax2 = max(LL[0], LL[1]);
        if (Lmax2 == 0) continue;

        // build WtB / qproj for both b's (sequential)
        #pragma unroll
        for (int m = 0; m < 2; m++) {
            if (tid < D) qs[tid] = q_all[(size_t)bb2[m] * D + tid];
            __syncthreads();
            unsigned* WtB = WtBB[m];
            for (int e = tid; e < 4096; e += 256) {
                int n = e & 63, kw = e >> 6;
                int d0 = 2 * kw, d1 = 2 * kw + 1;
                float v0 = W1[(128 + d0) * 64 + n] - W1[(256 + d0) * 64 + n] + qs[d0] * W1[(384 + d0) * 64 + n];
                float v1 = W1[(128 + d1) * 64 + n] - W1[(256 + d1) * 64 + n] + qs[d1] * W1[(384 + d1) * 64 + n];
                WtB[n * 64 + (kw ^ ((n & 7) << 2))] = packh2(v0, v1);
            }
            {
                int colq = tid >> 2, sq = tid & 3;
                float acc = 0.0f;
                int dbase = sq * 32;
                #pragma unroll 8
                for (int d = dbase; d < dbase + 32; d++)
                    acc += qs[d] * (W1[d * 64 + colq] + W1[(256 + d) * 64 + colq]);
                acc += __shfl_xor_sync(0xffffffffu, acc, 1);
                acc += __shfl_xor_sync(0xffffffffu, acc, 2);
                if (sq == 0) qprojS[m][colq] = acc;
            }
            __syncthreads();
        }

        // prefetch tile 0 for both
        float4 xa[2][4];
        #pragma unroll
        for (int m = 0; m < 2; m++) {
            if (r_st < LL[m]) {
                const float4* xp = (const float4*)&x[((size_t)bb2[m] * T + r_st) * D + c_st * 16];
                #pragma unroll
                for (int q4 = 0; q4 < 4; q4++) xa[m][q4] = xp[q4];
            } else {
                #pragma unroll
                for (int q4 = 0; q4 < 4; q4++) xa[m][q4] = make_float4(0.f, 0.f, 0.f, 0.f);
            }
        }

        int ntiles = (Lmax2 + 31) >> 5;
        for (int i = 0; i < ntiles; i++) {
            int t0 = i << 5;
            // stage both tiles
            #pragma unroll
            for (int m = 0; m < 2; m++) {
                if (t0 < LL[m]) {
                    unsigned wv[8];
                    #pragma unroll
                    for (int q4 = 0; q4 < 4; q4++) {
                        wv[q4 * 2 + 0] = packh2(xa[m][q4].x, xa[m][q4].y);
                        wv[q4 * 2 + 1] = packh2(xa[m][q4].z, xa[m][q4].w);
                    }
                    *(uint4*)&xkB[m][st_blockbase + st_lo]       = make_uint4(wv[0], wv[1], wv[2], wv[3]);
                    *(uint4*)&xkB[m][st_blockbase + (st_lo ^ 4)] = make_uint4(wv[4], wv[5], wv[6], wv[7]);
                }
            }
            __syncthreads();   // xk ready

            // prefetch next tiles
            #pragma unroll
            for (int m = 0; m < 2; m++) {
                int tnx = t0 + 32 + r_st;
                if (tnx < LL[m]) {
                    const float4* xp = (const float4*)&x[((size_t)bb2[m] * T + tnx) * D + c_st * 16];
                    #pragma unroll
                    for (int q4 = 0; q4 < 4; q4++) xa[m][q4] = xp[q4];
                } else {
                    #pragma unroll
                    for (int q4 = 0; q4 < 4; q4++) xa[m][q4] = make_float4(0.f, 0.f, 0.f, 0.f);
                }
            }

            // passes for both b's
            #pragma unroll
            for (int m = 0; m < 2; m++) {
                if (t0 >= LL[m]) continue;
                unsigned* xk   = xkB[m];
                unsigned* WtB  = WtBB[m];
                unsigned* xout = xoutB[m];
                unsigned* h1h  = h1hB[m];

                // pass 1: attention layer-1
                {
                    float acca[2][4];
                    float p0 = qprojS[m][w * 8 + 2 * tig], p1 = qprojS[m][w * 8 + 2 * tig + 1];
                    acca[0][0] = p0; acca[0][1] = p1; acca[0][2] = p0; acca[0][3] = p1;
                    acca[1][0] = p0; acca[1][1] = p1; acca[1][2] = p0; acca[1][3] = p1;
                    int nbatt = (w * 8 + g) * 64;
                    #pragma unroll
                    for (int s = 0; s < 8; s++) {
                        int k0 = (s * 8 + tig) ^ gsw, k1 = (s * 8 + tig + 4) ^ gsw;
                        unsigned a[2][4], bbv[2];
                        #pragma unroll
                        for (int mt = 0; mt < 2; mt++) {
                            int r0 = mt * 16 + g;
                            a[mt][0] = xk[r0 * 64 + k0];
                            a[mt][1] = xk[(r0 + 8) * 64 + k0];
                            a[mt][2] = xk[r0 * 64 + k1];
                            a[mt][3] = xk[(r0 + 8) * 64 + k1];
                        }
                        bbv[0] = WtB[nbatt + k0];
                        bbv[1] = WtB[nbatt + k1];
                        mma_f16(acca[0], a[0], bbv);
                        mma_f16(acca[1], a[1], bbv);
                    }
                    int col = w * 8 + 2 * tig;
                    float al0 = a1s[col], al1 = a1s[col + 1];
                    int chsw = ((w ^ g) << 2) + tig;
                    #pragma unroll
                    for (int mt = 0; mt < 2; mt++) {
                        int r0 = mt * 16 + g;
                        h1h[r0 * 32 + chsw]       = packh2(dicef(acca[mt][0], al0), dicef(acca[mt][1], al1));
                        h1h[(r0 + 8) * 32 + chsw] = packh2(dicef(acca[mt][2], al0), dicef(acca[mt][3], al1));
                    }
                }

                // pass 2: x-projection
                {
                    float acc[2][6][4];
                    #pragma unroll
                    for (int mt = 0; mt < 2; mt++)
                        #pragma unroll
                        for (int nt = 0; nt < 6; nt++)
                            #pragma unroll
                            for (int k = 0; k < 4; k++) acc[mt][nt][k] = 0.0f;

                    #pragma unroll
                    for (int s = 0; s < 8; s++) {
                        int k0 = (s * 8 + tig) ^ gsw, k1 = (s * 8 + tig + 4) ^ gsw;
                        unsigned a[2][4];
                        #pragma unroll
                        for (int mt = 0; mt < 2; mt++) {
                            int r0 = mt * 16 + g;
                            a[mt][0] = xk[r0 * 64 + k0];
                            a[mt][1] = xk[(r0 + 8) * 64 + k0];
                            a[mt][2] = xk[r0 * 64 + k1];
                            a[mt][3] = xk[(r0 + 8) * 64 + k1];
                        }
                        #pragma unroll
                        for (int nt = 0; nt < 6; nt++) {
                            mma_f16(acc[0][nt], a[0], wb[nt][s]);
                            mma_f16(acc[1][nt], a[1], wb[nt][s]);
                        }
                    }
                    #pragma unroll
                    for (int mt = 0; mt < 2; mt++)
                        #pragma unroll
                        for (int nt = 0; nt < 6; nt++) {
                            int cp = cperm[nt];
                            xout[(mt * 16 + g) * 196 + cp]     = packh2(acc[mt][nt][0], acc[mt][nt][1]);
                            xout[(mt * 16 + 8 + g) * 196 + cp] = packh2(acc[mt][nt][2], acc[mt][nt][3]);
                        }
                }
            }
            __syncthreads();   // h1h + xout ready (both)

            // epilogues for both b's
            #pragma unroll
            for (int m = 0; m < 2; m++) {
                if (t0 >= LL[m]) continue;
                if (w < 2) {
                    unsigned h1sa = (unsigned)__cvta_generic_to_shared(h1hB[m]);
                    int m0 = w * 16;
                    float acc2[2][4];
                    #pragma unroll
                    for (int nt = 0; nt < 2; nt++)
                        #pragma unroll
                        for (int k = 0; k < 4; k++) acc2[nt][k] = 0.0f;
                    unsigned baseH = h1sa + (unsigned)((m0 + rsel) * 128);
                    #pragma unroll
                    for (int s = 0; s < 4; s++) {
                        unsigned av[4];
                        ldsm_x4(av, baseH + (unsigned)((((2 * s + hi) ^ r8) << 4)));
                        mma_f16(acc2[0], av, w2b[0][s]);
                        mma_f16(acc2[1], av, w2b[1][s]);
                    }
                    float v0 = 0.0f, v1 = 0.0f;
                    #pragma unroll
                    for (int nt = 0; nt < 2; nt++) {
                        int c0 = nt * 8 + 2 * tig;
                        float wa = W3s[c0], wb3 = W3s[c0 + 1];
                        float aa = a2s[c0], ab = a2s[c0 + 1];
                        v0 += dicef(acc2[nt][0], aa) * wa + dicef(acc2[nt][1], ab) * wb3;
                        v1 += dicef(acc2[nt][2], aa) * wa + dicef(acc2[nt][3], ab) * wb3;
                    }
                    v0 += __shfl_xor_sync(0xffffffffu, v0, 1);
                    v0 += __shfl_xor_sync(0xffffffffu, v0, 2);
                    v1 += __shfl_xor_sync(0xffffffffu, v1, 1);
                    v1 += __shfl_xor_sync(0xffffffffu, v1, 2);
                    if (tig == 0) {
                        int trow0 = t0 + m0 + g;
                        int trow1 = trow0 + 8;
                        if (trow0 < LL[m]) g_att[(size_t)trow0 * B + bb2[m]] = sigt(v0);
                        if (trow1 < LL[m]) g_att[(size_t)trow1 * B + bb2[m]] = sigt(v1);
                    }
                } else {
                    unsigned* xout = xoutB[m];
                    int idx = tid - 64;          // 0..191
                    int r = idx / 6, c = idx % 6;
                    int t = t0 + r;
                    if (t < LL[m]) {
                        size_t gb = ((size_t)t * B + pp[m]) * 192;
                        #pragma unroll
                        for (int k = 0; k < 8; k++) {
                            uint4 v = *(uint4*)&xout[r * 196 + c * 4 + k * 24];
                            *(uint4*)&g_xproj[gb + c * 4 + k * 24] = v;
                        }
                    }
                }
            }
            __syncthreads();
        }
    }
}

// ---------------- AUGRU scan (R14: M=16, 256 blocks, 2 blocks/SM, B-frags from smem) ----
__global__ __launch_bounds__(256, 2) void k_augru(
    const int* __restrict__ slen,
    const float* __restrict__ Wu, const float* __restrict__ Wr, const float* __restrict__ Wc,
    float* __restrict__ out)
{
    extern __shared__ unsigned smw[];
    unsigned* hT  = smw + 24576;
    unsigned* rhT = smw + 25600;
    __shared__ int   Ls[16];
    __shared__ int   bis[16];
    __shared__ float atts[2][16];
    __shared__ int   LmaxS;

    int tid = threadIdx.x;

    for (int e = tid; e < 8192; e += 256) {
        int n = e & 127, kw = e >> 7;
        int sw = n * 64 + (kw ^ ((n & 7) << 2));
        smw[sw]         = packh2(Wu[16384 + (2 * kw) * 128 + n], Wu[16384 + (2 * kw + 1) * 128 + n]);
        smw[8192 + sw]  = packh2(Wr[16384 + (2 * kw) * 128 + n], Wr[16384 + (2 * kw + 1) * 128 + n]);
        smw[16384 + sw] = packh2(Wc[16384 + (2 * kw) * 128 + n], Wc[16384 + (2 * kw + 1) * 128 + n]);
    }
    for (int e = tid; e < 2048; e += 256) hT[e] = 0u;
    if (tid < 16) {
        int b = g_perm[blockIdx.x * 16 + tid];
        bis[tid] = b;
        int L = slen[b]; L = min(max(L, 0), T);
        Ls[tid] = L;
    }
    __syncthreads();
    if (tid == 0) { int m = 0; for (int i = 0; i < 16; i++) m = max(m, Ls[i]); LmaxS = m; }
    __syncthreads();
    const int Lmax = LmaxS;
    const int p0 = blockIdx.x * 16;

    const int w = tid >> 5, lane = tid & 31, g = lane >> 2, tig = lane & 3;
    const int gsw = g << 2;
    const int n0w = w * 16;

    const int sub = lane >> 3, r8 = lane & 7;
    const int hi = sub >> 1;
    const int rsel = (sub & 1) * 8 + r8;
    unsigned hTsa = (unsigned)__cvta_generic_to_shared(hT);
    unsigned baseA = hTsa + (unsigned)(rsel * 256);

    int nb0 = (n0w + g) * 64;
    int nb1 = (n0w + 8 + g) * 64;

    int stoff[2];
    #pragma unroll
    for (int nt = 0; nt < 2; nt++) stoff[nt] = (((w * 2 + nt) ^ g) << 2) + tig;

    int myL[2];
    #pragma unroll
    for (int half = 0; half < 2; half++) myL[half] = Ls[half * 8 + g];

    float hm[2][4];
    #pragma unroll
    for (int nt = 0; nt < 2; nt++)
        #pragma unroll
        for (int k = 0; k < 4; k++) hm[nt][k] = 0.0f;

    const int coff = (w * 4 + tig) * 6;

    unsigned xal[2][2][3];
    {
        #pragma unroll
        for (int half = 0; half < 2; half++) {
            size_t rb = ((size_t)p0 + half * 8 + g) * 192 + coff;
            uint2 v0 = *(const uint2*)&g_xproj[rb];
            uint2 v1 = *(const uint2*)&g_xproj[rb + 2];
            uint2 v2 = *(const uint2*)&g_xproj[rb + 4];
            xal[half][0][0] = v0.x; xal[half][1][0] = v0.y;
            xal[half][0][1] = v1.x; xal[half][1][1] = v1.y;
            xal[half][0][2] = v2.x; xal[half][1][2] = v2.y;
        }
        if (tid < 16) atts[0][tid] = g_att[(size_t)0 * B + bis[tid]];
    }
    __syncthreads();

    for (int t = 0; t < Lmax; t++) {
        int cur = t & 1, nxt = cur ^ 1;
        int tn = min(t + 1, T - 1);

        unsigned xaln[2][2][3];
        {
            size_t tbn = (size_t)tn * B + p0;
            #pragma unroll
            for (int half = 0; half < 2; half++) {
                size_t rbn = (tbn + half * 8 + g) * 192 + coff;
                uint2 v0 = *(const uint2*)&g_xproj[rbn];
                uint2 v1 = *(const uint2*)&g_xproj[rbn + 2];
                uint2 v2 = *(const uint2*)&g_xproj[rbn + 4];
                xaln[half][0][0] = v0.x; xaln[half][1][0] = v0.y;
                xaln[half][0][1] = v1.x; xaln[half][1][1] = v1.y;
                xaln[half][0][2] = v2.x; xaln[half][1][2] = v2.y;
            }
        }
        float attn_v = 0.0f;
        if (tid < 16) attn_v = g_att[(size_t)tn * B + bis[tid]];

        float accU[2][4], accR[2][4];
        #pragma unroll
        for (int nt = 0; nt < 2; nt++)
            #pragma unroll
            for (int k = 0; k < 4; k++) { accU[nt][k] = 0.0f; accR[nt][k] = 0.0f; }

        #pragma unroll
        for (int s = 0; s < 8; s++) {
            unsigned choff = (unsigned)((((2 * s + hi) ^ r8) << 4));
            unsigned ah[4];
            ldsm_x4(ah, baseA + choff);
            int k0 = (s * 8 + tig) ^ gsw, k1 = (s * 8 + tig + 4) ^ gsw;
            {
                unsigned bu[2] = { smw[nb0 + k0], smw[nb0 + k1] };
                unsigned br[2] = { smw[8192 + nb0 + k0], smw[8192 + nb0 + k1] };
                mma_f16(accU[0], ah, bu);
                mma_f16(accR[0], ah, br);
            }
            {
                unsigned bu[2] = { smw[nb1 + k0], smw[nb1 + k1] };
                unsigned br[2] = { smw[8192 + nb1 + k0], smw[8192 + nb1 + k1] };
                mma_f16(accU[1], ah, bu);
                mma_f16(accR[1], ah, br);
            }
        }

        float uu[2][4];
        #pragma unroll
        for (int nt = 0; nt < 2; nt++)
            #pragma unroll
            for (int half = 0; half < 2; half++) {
                int row = half * 8 + g;
                float2 xu = unpackh2(xal[half][nt][0]);
                float2 xr = unpackh2(xal[half][nt][1]);
                float2 uv = sig2(accU[nt][half * 2 + 0] + xu.x, accU[nt][half * 2 + 1] + xu.y);
                float2 rv = sig2(accR[nt][half * 2 + 0] + xr.x, accR[nt][half * 2 + 1] + xr.y);
                uu[nt][half * 2 + 0] = uv.x;
                uu[nt][half * 2 + 1] = uv.y;
                rhT[row * 64 + stoff[nt]] =
                    packh2(rv.x * hm[nt][half * 2 + 0], rv.y * hm[nt][half * 2 + 1]);
            }
        if (tid < 16) atts[nxt][tid] = attn_v;
        __syncthreads();

        float accC[2][4];
        #pragma unroll
        for (int nt = 0; nt < 2; nt++)
            #pragma unroll
            for (int half = 0; half < 2; half++) {
                float2 xc = unpackh2(xal[half][nt][2]);
                accC[nt][half * 2 + 0] = xc.x;
                accC[nt][half * 2 + 1] = xc.y;
            }

        #pragma unroll
        for (int s = 0; s < 8; s++) {
            unsigned choff = (unsigned)((((2 * s + hi) ^ r8) << 4)) + 4096u;
            unsigned ar[4];
            ldsm_x4(ar, baseA + choff);
            int k0 = (s * 8 + tig) ^ gsw, k1 = (s * 8 + tig + 4) ^ gsw;
            {
                unsigned bc[2] = { smw[16384 + nb0 + k0], smw[16384 + nb0 + k1] };
                mma_f16(accC[0], ar, bc);
            }
            {
                unsigned bc[2] = { smw[16384 + nb1 + k0], smw[16384 + nb1 + k1] };
                mma_f16(accC[1], ar, bc);
            }
        }

        #pragma unroll
        for (int nt = 0; nt < 2; nt++)
            #pragma unroll
            for (int half = 0; half < 2; half++) {
                int row = half * 8 + g;
                if (t < myL[half]) {
                    float a_att = atts[cur][row];
                    float c0 = tanha(accC[nt][half * 2 + 0]);
                    float c1 = tanha(accC[nt][half * 2 + 1]);
                    float ut0 = uu[nt][half * 2 + 0] * a_att;
                    float ut1 = uu[nt][half * 2 + 1] * a_att;
                    hm[nt][half * 2 + 0] += ut0 * (c0 - hm[nt][half * 2 + 0]);
                    hm[nt][half * 2 + 1] += ut1 * (c1 - hm[nt][half * 2 + 1]);
                }
                hT[row * 64 + stoff[nt]] =
                    packh2(hm[nt][half * 2 + 0], hm[nt][half * 2 + 1]);
            }
        __syncthreads();

        #pragma unroll
        for (int half = 0; half < 2; half++)
            #pragma unroll
            for (int nt = 0; nt < 2; nt++)
                #pragma unroll
                for (int gt = 0; gt < 3; gt++)
                    xal[half][nt][gt] = xaln[half][nt][gt];
    }

    #pragma unroll
    for (int nt = 0; nt < 2; nt++) {
        int col = n0w + nt * 8 + tig * 2;
        #pragma unroll
        for (int half = 0; half < 2; half++) {
            int row = half * 8 + g;
            size_t base = (size_t)bis[row] * U + col;
            out[base]     = hm[nt][half * 2 + 0];
            out[base + 1] = hm[nt][half * 2 + 1];
        }
    }
}

// ---------------- launch ----------------
extern "C" void kernel_launch(void* const* d_in, const int* in_sizes, int n_in,
                              void* d_out, int out_size)
{
    const float* x    = (const float*)d_in[0];
    const float* q    = (const float*)d_in[1];
    const int*   slen = (const int*)d_in[2];
    const float* W1   = (const float*)d_in[3];
    const float* a1   = (const float*)d_in[4];
    const float* W2   = (const float*)d_in[5];
    const float* a2   = (const float*)d_in[6];
    const float* W3   = (const float*)d_in[7];
    const float* Wu   = (const float*)d_in[8];
    const float* Wr   = (const float*)d_in[9];
    const float* Wc   = (const float*)d_in[10];
    float* out = (float*)d_out;

    const int FUSED_SMEM = 26880 * 4;     // 107,520 B
    const int AUGRU_SMEM = 26624 * 4;     // 106,496 B (2 blocks/SM)

    cudaFuncSetAttribute(k_fused, cudaFuncAttributeMaxDynamicSharedMemorySize, FUSED_SMEM);
    cudaFuncSetAttribute(k_augru, cudaFuncAttributeMaxDynamicSharedMemorySize, AUGRU_SMEM);

    k_sort<<<1, 512>>>(slen);
    k_fused<<<512, 256, FUSED_SMEM>>>(x, q, slen, W1, a1, W2, a2, W3, Wu, Wr, Wc);
    k_augru<<<B / 16, 256, AUGRU_SMEM>>>(slen, Wu, Wr, Wc, out);
}

// round 16
// speedup vs baseline: 1.1763x; 1.0027x over previous
#include <cuda_runtime.h>
#include <cuda_fp16.h>
#include <math.h>

#define B 4096
#define T 200
#define D 128
#define U 128

// ---------------- device scratch ----------------
__device__ __align__(128) float g_att[(size_t)T * B];                  // [t][b_orig]
__device__ __align__(128) unsigned g_xproj[(size_t)T * B * 192];       // [t][p_sorted][perm] half2
__device__ __align__(128) unsigned g_wbh[24576];                       // xproj weights, fp16 B-layout swizzled
__device__ int g_perm[B];

__device__ __forceinline__ float sigt(float x) {
    float t;
    asm("tanh.approx.f32 %0, %1;" : "=f"(t) : "f"(0.5f * x));
    return fmaf(0.5f, t, 0.5f);
}
__device__ __forceinline__ float2 sig2(float a, float b) {
    __half2 p = __floats2half2_rn(0.5f * a, 0.5f * b);
    unsigned pu = *(unsigned*)&p, r;
    asm("tanh.approx.f16x2 %0, %1;" : "=r"(r) : "r"(pu));
    float2 t = __half22float2(*(__half2*)&r);
    return make_float2(fmaf(0.5f, t.x, 0.5f), fmaf(0.5f, t.y, 0.5f));
}
__device__ __forceinline__ float tanha(float x) {
    float t;
    asm("tanh.approx.f32 %0, %1;" : "=f"(t) : "f"(x));
    return t;
}
__device__ __forceinline__ float dicef(float x, float alpha) {
    float p = sigt(x);
    return p * x + alpha * (1.0f - p) * x;
}
__device__ __forceinline__ unsigned packh2(float a, float b) {
    __half2 h = __floats2half2_rn(a, b);
    return *(unsigned*)&h;
}
__device__ __forceinline__ float2 unpackh2(unsigned u) {
    return __half22float2(*(__half2*)&u);
}
__device__ __forceinline__ void mma_f16(float c[4], const unsigned a[4], const unsigned b[2]) {
    asm("mma.sync.aligned.m16n8k16.row.col.f32.f16.f16.f32 "
        "{%0,%1,%2,%3}, {%4,%5,%6,%7}, {%8,%9}, {%0,%1,%2,%3};\n"
        : "+f"(c[0]), "+f"(c[1]), "+f"(c[2]), "+f"(c[3])
        : "r"(a[0]), "r"(a[1]), "r"(a[2]), "r"(a[3]), "r"(b[0]), "r"(b[1]));
}
__device__ __forceinline__ void ldsm_x4(unsigned r[4], unsigned saddr) {
    asm volatile("ldmatrix.sync.aligned.m8n8.x4.shared.b16 {%0,%1,%2,%3}, [%4];"
        : "=r"(r[0]), "=r"(r[1]), "=r"(r[2]), "=r"(r[3]) : "r"(saddr));
}

// ---------------- counting sort (ascending) ----------------
__global__ __launch_bounds__(512) void k_sort(const int* __restrict__ slen) {
    __shared__ int cnt[256];
    __shared__ int off[256];
    int tid = threadIdx.x;
    if (tid < 256) cnt[tid] = 0;
    __syncthreads();
    for (int b = tid; b < B; b += 512) {
        int L = slen[b]; L = min(max(L, 0), T);
        atomicAdd(&cnt[L], 1);
    }
    __syncthreads();
    if (tid == 0) {
        int acc = 0;
        for (int i = 0; i <= T; i++) { off[i] = acc; acc += cnt[i]; }
    }
    __syncthreads();
    for (int b = tid; b < B; b += 512) {
        int L = slen[b]; L = min(max(L, 0), T);
        int pos = atomicAdd(&off[L], 1);
        g_perm[pos] = b;
    }
}

// ---------------- weight prep: xproj weights -> global fp16 B-layout ----------------
__global__ __launch_bounds__(256) void k_prepw(
    const float* __restrict__ Wu, const float* __restrict__ Wr, const float* __restrict__ Wc)
{
    int e = blockIdx.x * 256 + threadIdx.x;     // 0..24575
    int m = e >> 13, r = e & 8191;
    int n = r & 127, kw = r >> 7;
    const float* S = (m == 0) ? Wu : (m == 1) ? Wr : Wc;
    g_wbh[m * 8192 + n * 64 + (kw ^ ((n & 7) << 2))] =
        packh2(S[(2 * kw) * 128 + n], S[(2 * kw + 1) * 128 + n]);
}

// ---------------- fused attention + x-projection: 2 blocks/SM, B-frags from L1/global ----
// dyn smem words: WtB @0 (4096), xk @4096 (2048), xout @6144 (6272), h1h @12416 (1024) = 13440
__global__ __launch_bounds__(256, 2) void k_fused(
    const float* __restrict__ x, const float* __restrict__ q_all,
    const int* __restrict__ slen,
    const float* __restrict__ W1, const float* __restrict__ a1,
    const float* __restrict__ W2, const float* __restrict__ a2,
    const float* __restrict__ W3)
{
    extern __shared__ unsigned smw[];
    unsigned* WtB  = smw;
    unsigned* xk   = smw + 4096;
    unsigned* xout = smw + 6144;
    unsigned* h1h  = smw + 12416;
    __shared__ unsigned W2h[16 * 32];
    __shared__ float a1s[64], a2s[16], W3s[16];
    __shared__ float qs[D], qproj[64];

    int tid = threadIdx.x;
    if (tid < 64) a1s[tid] = a1[tid];
    if (tid < 16) { a2s[tid] = a2[tid]; W3s[tid] = W3[tid]; }
    for (int e = tid; e < 512; e += 256) {
        int n = e & 15, kw = e >> 4;
        W2h[n * 32 + (kw ^ ((n & 7) << 2))] = packh2(W2[(2 * kw) * 16 + n], W2[(2 * kw + 1) * 16 + n]);
    }
    __syncthreads();

    const int w = tid >> 5, lane = tid & 31, g = lane >> 2, tig = lane & 3;
    const int gsw = g << 2;
    const int sub = lane >> 3, r8 = lane & 7;
    const int hi = sub >> 1;
    const int rsel = (sub & 1) * 8 + r8;

    // layer-2 B-fragments in regs (small)
    unsigned w2b[2][4][2];
    #pragma unroll
    for (int nt = 0; nt < 2; nt++) {
        int nb2 = (nt * 8 + g) * 32;
        #pragma unroll
        for (int s = 0; s < 4; s++) {
            w2b[nt][s][0] = W2h[nb2 + ((s * 8 + tig) ^ gsw)];
            w2b[nt][s][1] = W2h[nb2 + ((s * 8 + tig + 4) ^ gsw)];
        }
    }
    // xproj B-frag global bases + permuted output cols
    int nbv[6], cperm[6];
    #pragma unroll
    for (int nt = 0; nt < 6; nt++) {
        int col = w * 48 + nt * 8 + g;
        nbv[nt] = (col >> 7) * 8192 + (col & 127) * 64;
        int W = w * 24 + nt * 4 + tig;
        int gate = W >> 6, kk = W & 63;
        cperm[nt] = ((kk >> 3) * 4 + (kk & 3)) * 6 + gate * 2 + ((kk >> 2) & 1);
    }

    unsigned h1sa = (unsigned)__cvta_generic_to_shared(h1h);
    const int r_st = tid >> 3, c_st = tid & 7;
    const int rs_st = (r_st & 7) << 2;

    for (int j = 0; j < 8; j++) {
        int p = blockIdx.x + j * 512;
        int b = g_perm[p];
        int L = slen[b]; L = min(max(L, 0), T);
        if (L == 0) continue;

        if (tid < D) qs[tid] = q_all[(size_t)b * D + tid];
        __syncthreads();

        for (int e = tid; e < 4096; e += 256) {
            int n = e & 63, kw = e >> 6;
            int d0 = 2 * kw, d1 = 2 * kw + 1;
            float v0 = W1[(128 + d0) * 64 + n] - W1[(256 + d0) * 64 + n] + qs[d0] * W1[(384 + d0) * 64 + n];
            float v1 = W1[(128 + d1) * 64 + n] - W1[(256 + d1) * 64 + n] + qs[d1] * W1[(384 + d1) * 64 + n];
            WtB[n * 64 + (kw ^ ((n & 7) << 2))] = packh2(v0, v1);
        }
        {
            int colq = tid >> 2, sq = tid & 3;
            float acc = 0.0f;
            int dbase = sq * 32;
            #pragma unroll 8
            for (int d = dbase; d < dbase + 32; d++)
                acc += qs[d] * (W1[d * 64 + colq] + W1[(256 + d) * 64 + colq]);
            acc += __shfl_xor_sync(0xffffffffu, acc, 1);
            acc += __shfl_xor_sync(0xffffffffu, acc, 2);
            if (sq == 0) qproj[colq] = acc;
        }

        // prefetch tile 0 (streaming hint: keep weights resident in L1)
        float4 xa[4];
        if (r_st < L) {
            const float4* xp = (const float4*)&x[((size_t)b * T + r_st) * D + c_st * 16];
            #pragma unroll
            for (int q4 = 0; q4 < 4; q4++) xa[q4] = __ldcs(xp + q4);
        } else {
            #pragma unroll
            for (int q4 = 0; q4 < 4; q4++) xa[q4] = make_float4(0.f, 0.f, 0.f, 0.f);
        }
        __syncthreads();

        for (int t0 = 0; t0 < L; t0 += 32) {
            {
                unsigned wv[8];
                #pragma unroll
                for (int q4 = 0; q4 < 4; q4++) {
                    wv[q4 * 2 + 0] = packh2(xa[q4].x, xa[q4].y);
                    wv[q4 * 2 + 1] = packh2(xa[q4].z, xa[q4].w);
                }
                int blockbase = r_st * 64 + ((c_st * 8) ^ (rs_st & 24));
                int lo = rs_st & 4;
                *(uint4*)&xk[blockbase + lo]       = make_uint4(wv[0], wv[1], wv[2], wv[3]);
                *(uint4*)&xk[blockbase + (lo ^ 4)] = make_uint4(wv[4], wv[5], wv[6], wv[7]);
            }
            __syncthreads();   // xk ready

            {
                int tnx = t0 + 32 + r_st;
                if (tnx < L) {
                    const float4* xp = (const float4*)&x[((size_t)b * T + tnx) * D + c_st * 16];
                    #pragma unroll
                    for (int q4 = 0; q4 < 4; q4++) xa[q4] = __ldcs(xp + q4);
                } else {
                    #pragma unroll
                    for (int q4 = 0; q4 < 4; q4++) xa[q4] = make_float4(0.f, 0.f, 0.f, 0.f);
                }
            }

            // pass 1: attention layer-1 (B from smem WtB)
            {
                float acca[2][4];
                float p0 = qproj[w * 8 + 2 * tig], p1 = qproj[w * 8 + 2 * tig + 1];
                acca[0][0] = p0; acca[0][1] = p1; acca[0][2] = p0; acca[0][3] = p1;
                acca[1][0] = p0; acca[1][1] = p1; acca[1][2] = p0; acca[1][3] = p1;
                int nbatt = (w * 8 + g) * 64;
                #pragma unroll
                for (int s = 0; s < 8; s++) {
                    int k0 = (s * 8 + tig) ^ gsw, k1 = (s * 8 + tig + 4) ^ gsw;
                    unsigned a[2][4], bbv[2];
                    #pragma unroll
                    for (int mt = 0; mt < 2; mt++) {
                        int r0 = mt * 16 + g;
                        a[mt][0] = xk[r0 * 64 + k0];
                        a[mt][1] = xk[(r0 + 8) * 64 + k0];
                        a[mt][2] = xk[r0 * 64 + k1];
                        a[mt][3] = xk[(r0 + 8) * 64 + k1];
                    }
                    bbv[0] = WtB[nbatt + k0];
                    bbv[1] = WtB[nbatt + k1];
                    mma_f16(acca[0], a[0], bbv);
                    mma_f16(acca[1], a[1], bbv);
                }
                int col = w * 8 + 2 * tig;
                float al0 = a1s[col], al1 = a1s[col + 1];
                int chsw = ((w ^ g) << 2) + tig;
                #pragma unroll
                for (int mt = 0; mt < 2; mt++) {
                    int r0 = mt * 16 + g;
                    h1h[r0 * 32 + chsw]       = packh2(dicef(acca[mt][0], al0), dicef(acca[mt][1], al1));
                    h1h[(r0 + 8) * 32 + chsw] = packh2(dicef(acca[mt][2], al0), dicef(acca[mt][3], al1));
                }
            }

            // pass 2: x-projection (B-frags streamed from g_wbh via L1)
            {
                float acc[2][6][4];
                #pragma unroll
                for (int mt = 0; mt < 2; mt++)
                    #pragma unroll
                    for (int nt = 0; nt < 6; nt++)
                        #pragma unroll
                        for (int k = 0; k < 4; k++) acc[mt][nt][k] = 0.0f;

                #pragma unroll
                for (int s = 0; s < 8; s++) {
                    int k0 = (s * 8 + tig) ^ gsw, k1 = (s * 8 + tig + 4) ^ gsw;
                    unsigned a[2][4];
                    #pragma unroll
                    for (int mt = 0; mt < 2; mt++) {
                        int r0 = mt * 16 + g;
                        a[mt][0] = xk[r0 * 64 + k0];
                        a[mt][1] = xk[(r0 + 8) * 64 + k0];
                        a[mt][2] = xk[r0 * 64 + k1];
                        a[mt][3] = xk[(r0 + 8) * 64 + k1];
                    }
                    unsigned bbv[6][2];
                    #pragma unroll
                    for (int nt = 0; nt < 6; nt++) {
                        bbv[nt][0] = g_wbh[nbv[nt] + k0];
                        bbv[nt][1] = g_wbh[nbv[nt] + k1];
                    }
                    #pragma unroll
                    for (int nt = 0; nt < 6; nt++) {
                        mma_f16(acc[0][nt], a[0], bbv[nt]);
                        mma_f16(acc[1][nt], a[1], bbv[nt]);
                    }
                }
                #pragma unroll
                for (int mt = 0; mt < 2; mt++)
                    #pragma unroll
                    for (int nt = 0; nt < 6; nt++) {
                        int cp = cperm[nt];
                        xout[(mt * 16 + g) * 196 + cp]     = packh2(acc[mt][nt][0], acc[mt][nt][1]);
                        xout[(mt * 16 + 8 + g) * 196 + cp] = packh2(acc[mt][nt][2], acc[mt][nt][3]);
                    }
            }
            __syncthreads();

            if (w < 2) {
                int m0 = w * 16;
                float acc2[2][4];
                #pragma unroll
                for (int nt = 0; nt < 2; nt++)
                    #pragma unroll
                    for (int k = 0; k < 4; k++) acc2[nt][k] = 0.0f;
                unsigned baseH = h1sa + (unsigned)((m0 + rsel) * 128);
                #pragma unroll
                for (int s = 0; s < 4; s++) {
                    unsigned av[4];
                    ldsm_x4(av, baseH + (unsigned)((((2 * s + hi) ^ r8) << 4)));
                    mma_f16(acc2[0], av, w2b[0][s]);
                    mma_f16(acc2[1], av, w2b[1][s]);
                }
                float v0 = 0.0f, v1 = 0.0f;
                #pragma unroll
                for (int nt = 0; nt < 2; nt++) {
                    int c0 = nt * 8 + 2 * tig;
                    float wa = W3s[c0], wb3 = W3s[c0 + 1];
                    float aa = a2s[c0], ab = a2s[c0 + 1];
                    v0 += dicef(acc2[nt][0], aa) * wa + dicef(acc2[nt][1], ab) * wb3;
                    v1 += dicef(acc2[nt][2], aa) * wa + dicef(acc2[nt][3], ab) * wb3;
                }
                v0 += __shfl_xor_sync(0xffffffffu, v0, 1);
                v0 += __shfl_xor_sync(0xffffffffu, v0, 2);
                v1 += __shfl_xor_sync(0xffffffffu, v1, 1);
                v1 += __shfl_xor_sync(0xffffffffu, v1, 2);
                if (tig == 0) {
                    int trow0 = t0 + m0 + g;
                    int trow1 = trow0 + 8;
                    if (trow0 < L) g_att[(size_t)trow0 * B + b] = sigt(v0);
                    if (trow1 < L) g_att[(size_t)trow1 * B + b] = sigt(v1);
                }
            } else {
                int idx = tid - 64;
                int r = idx / 6, c = idx % 6;
                int t = t0 + r;
                if (t < L) {
                    size_t gb = ((size_t)t * B + p) * 192;
                    #pragma unroll
                    for (int k = 0; k < 8; k++) {
                        uint4 v = *(uint4*)&xout[r * 196 + c * 4 + k * 24];
                        __stcs((uint4*)&g_xproj[gb + c * 4 + k * 24], v);
                    }
                }
            }
            __syncthreads();
        }
    }
}

// ---------------- AUGRU scan (R14: M=16, 256 blocks, 2 blocks/SM, B-frags from smem) ----
__global__ __launch_bounds__(256, 2) void k_augru(
    const int* __restrict__ slen,
    const float* __restrict__ Wu, const float* __restrict__ Wr, const float* __restrict__ Wc,
    float* __restrict__ out)
{
    extern __shared__ unsigned smw[];
    unsigned* hT  = smw + 24576;
    unsigned* rhT = smw + 25600;
    __shared__ int   Ls[16];
    __shared__ int   bis[16];
    __shared__ float atts[2][16];
    __shared__ int   LmaxS;

    int tid = threadIdx.x;

    for (int e = tid; e < 8192; e += 256) {
        int n = e & 127, kw = e >> 7;
        int sw = n * 64 + (kw ^ ((n & 7) << 2));
        smw[sw]         = packh2(Wu[16384 + (2 * kw) * 128 + n], Wu[16384 + (2 * kw + 1) * 128 + n]);
        smw[8192 + sw]  = packh2(Wr[16384 + (2 * kw) * 128 + n], Wr[16384 + (2 * kw + 1) * 128 + n]);
        smw[16384 + sw] = packh2(Wc[16384 + (2 * kw) * 128 + n], Wc[16384 + (2 * kw + 1) * 128 + n]);
    }
    for (int e = tid; e < 2048; e += 256) hT[e] = 0u;
    if (tid < 16) {
        int b = g_perm[blockIdx.x * 16 + tid];
        bis[tid] = b;
        int L = slen[b]; L = min(max(L, 0), T);
        Ls[tid] = L;
    }
    __syncthreads();
    if (tid == 0) { int m = 0; for (int i = 0; i < 16; i++) m = max(m, Ls[i]); LmaxS = m; }
    __syncthreads();
    const int Lmax = LmaxS;
    const int p0 = blockIdx.x * 16;

    const int w = tid >> 5, lane = tid & 31, g = lane >> 2, tig = lane & 3;
    const int gsw = g << 2;
    const int n0w = w * 16;

    const int sub = lane >> 3, r8 = lane & 7;
    const int hi = sub >> 1;
    const int rsel = (sub & 1) * 8 + r8;
    unsigned hTsa = (unsigned)__cvta_generic_to_shared(hT);
    unsigned baseA = hTsa + (unsigned)(rsel * 256);

    int nb0 = (n0w + g) * 64;
    int nb1 = (n0w + 8 + g) * 64;

    int stoff[2];
    #pragma unroll
    for (int nt = 0; nt < 2; nt++) stoff[nt] = (((w * 2 + nt) ^ g) << 2) + tig;

    int myL[2];
    #pragma unroll
    for (int half = 0; half < 2; half++) myL[half] = Ls[half * 8 + g];

    float hm[2][4];
    #pragma unroll
    for (int nt = 0; nt < 2; nt++)
        #pragma unroll
        for (int k = 0; k < 4; k++) hm[nt][k] = 0.0f;

    const int coff = (w * 4 + tig) * 6;

    unsigned xal[2][2][3];
    {
        #pragma unroll
        for (int half = 0; half < 2; half++) {
            size_t rb = ((size_t)p0 + half * 8 + g) * 192 + coff;
            uint2 v0 = *(const uint2*)&g_xproj[rb];
            uint2 v1 = *(const uint2*)&g_xproj[rb + 2];
            uint2 v2 = *(const uint2*)&g_xproj[rb + 4];
            xal[half][0][0] = v0.x; xal[half][1][0] = v0.y;
            xal[half][0][1] = v1.x; xal[half][1][1] = v1.y;
            xal[half][0][2] = v2.x; xal[half][1][2] = v2.y;
        }
        if (tid < 16) atts[0][tid] = g_att[(size_t)0 * B + bis[tid]];
    }
    __syncthreads();

    for (int t = 0; t < Lmax; t++) {
        int cur = t & 1, nxt = cur ^ 1;
        int tn = min(t + 1, T - 1);

        unsigned xaln[2][2][3];
        {
            size_t tbn = (size_t)tn * B + p0;
            #pragma unroll
            for (int half = 0; half < 2; half++) {
                size_t rbn = (tbn + half * 8 + g) * 192 + coff;
                uint2 v0 = *(const uint2*)&g_xproj[rbn];
                uint2 v1 = *(const uint2*)&g_xproj[rbn + 2];
                uint2 v2 = *(const uint2*)&g_xproj[rbn + 4];
                xaln[half][0][0] = v0.x; xaln[half][1][0] = v0.y;
                xaln[half][0][1] = v1.x; xaln[half][1][1] = v1.y;
                xaln[half][0][2] = v2.x; xaln[half][1][2] = v2.y;
            }
        }
        float attn_v = 0.0f;
        if (tid < 16) attn_v = g_att[(size_t)tn * B + bis[tid]];

        float accU[2][4], accR[2][4];
        #pragma unroll
        for (int nt = 0; nt < 2; nt++)
            #pragma unroll
            for (int k = 0; k < 4; k++) { accU[nt][k] = 0.0f; accR[nt][k] = 0.0f; }

        #pragma unroll
        for (int s = 0; s < 8; s++) {
            unsigned choff = (unsigned)((((2 * s + hi) ^ r8) << 4));
            unsigned ah[4];
            ldsm_x4(ah, baseA + choff);
            int k0 = (s * 8 + tig) ^ gsw, k1 = (s * 8 + tig + 4) ^ gsw;
            {
                unsigned bu[2] = { smw[nb0 + k0], smw[nb0 + k1] };
                unsigned br[2] = { smw[8192 + nb0 + k0], smw[8192 + nb0 + k1] };
                mma_f16(accU[0], ah, bu);
                mma_f16(accR[0], ah, br);
            }
            {
                unsigned bu[2] = { smw[nb1 + k0], smw[nb1 + k1] };
                unsigned br[2] = { smw[8192 + nb1 + k0], smw[8192 + nb1 + k1] };
                mma_f16(accU[1], ah, bu);
                mma_f16(accR[1], ah, br);
            }
        }

        float uu[2][4];
        #pragma unroll
        for (int nt = 0; nt < 2; nt++)
            #pragma unroll
            for (int half = 0; half < 2; half++) {
                int row = half * 8 + g;
                float2 xu = unpackh2(xal[half][nt][0]);
                float2 xr = unpackh2(xal[half][nt][1]);
                float2 uv = sig2(accU[nt][half * 2 + 0] + xu.x, accU[nt][half * 2 + 1] + xu.y);
                float2 rv = sig2(accR[nt][half * 2 + 0] + xr.x, accR[nt][half * 2 + 1] + xr.y);
                uu[nt][half * 2 + 0] = uv.x;
                uu[nt][half * 2 + 1] = uv.y;
                rhT[row * 64 + stoff[nt]] =
                    packh2(rv.x * hm[nt][half * 2 + 0], rv.y * hm[nt][half * 2 + 1]);
            }
        if (tid < 16) atts[nxt][tid] = attn_v;
        __syncthreads();

        float accC[2][4];
        #pragma unroll
        for (int nt = 0; nt < 2; nt++)
            #pragma unroll
            for (int half = 0; half < 2; half++) {
                float2 xc = unpackh2(xal[half][nt][2]);
                accC[nt][half * 2 + 0] = xc.x;
                accC[nt][half * 2 + 1] = xc.y;
            }

        #pragma unroll
        for (int s = 0; s < 8; s++) {
            unsigned choff = (unsigned)((((2 * s + hi) ^ r8) << 4)) + 4096u;
            unsigned ar[4];
            ldsm_x4(ar, baseA + choff);
            int k0 = (s * 8 + tig) ^ gsw, k1 = (s * 8 + tig + 4) ^ gsw;
            {
                unsigned bc[2] = { smw[16384 + nb0 + k0], smw[16384 + nb0 + k1] };
                mma_f16(accC[0], ar, bc);
            }
            {
                unsigned bc[2] = { smw[16384 + nb1 + k0], smw[16384 + nb1 + k1] };
                mma_f16(accC[1], ar, bc);
            }
        }

        #pragma unroll
        for (int nt = 0; nt < 2; nt++)
            #pragma unroll
            for (int half = 0; half < 2; half++) {
                int row = half * 8 + g;
                if (t < myL[half]) {
                    float a_att = atts[cur][row];
                    float c0 = tanha(accC[nt][half * 2 + 0]);
                    float c1 = tanha(accC[nt][half * 2 + 1]);
                    float ut0 = uu[nt][half * 2 + 0] * a_att;
                    float ut1 = uu[nt][half * 2 + 1] * a_att;
                    hm[nt][half * 2 + 0] += ut0 * (c0 - hm[nt][half * 2 + 0]);
                    hm[nt][half * 2 + 1] += ut1 * (c1 - hm[nt][half * 2 + 1]);
                }
                hT[row * 64 + stoff[nt]] =
                    packh2(hm[nt][half * 2 + 0], hm[nt][half * 2 + 1]);
            }
        __syncthreads();

        #pragma unroll
        for (int half = 0; half < 2; half++)
            #pragma unroll
            for (int nt = 0; nt < 2; nt++)
                #pragma unroll
                for (int gt = 0; gt < 3; gt++)
                    xal[half][nt][gt] = xaln[half][nt][gt];
    }

    #pragma unroll
    for (int nt = 0; nt < 2; nt++) {
        int col = n0w + nt * 8 + tig * 2;
        #pragma unroll
        for (int half = 0; half < 2; half++) {
            int row = half * 8 + g;
            size_t base = (size_t)bis[row] * U + col;
            out[base]     = hm[nt][half * 2 + 0];
            out[base + 1] = hm[nt][half * 2 + 1];
        }
    }
}

// ---------------- launch ----------------
extern "C" void kernel_launch(void* const* d_in, const int* in_sizes, int n_in,
                              void* d_out, int out_size)
{
    const float* x    = (const float*)d_in[0];
    const float* q    = (const float*)d_in[1];
    const int*   slen = (const int*)d_in[2];
    const float* W1   = (const float*)d_in[3];
    const float* a1   = (const float*)d_in[4];
    const float* W2   = (const float*)d_in[5];
    const float* a2   = (const float*)d_in[6];
    const float* W3   = (const float*)d_in[7];
    const float* Wu   = (const float*)d_in[8];
    const float* Wr   = (const float*)d_in[9];
    const float* Wc   = (const float*)d_in[10];
    float* out = (float*)d_out;

    const int FUSED_SMEM = 13440 * 4;     //  53,760 B (2 blocks/SM)
    const int AUGRU_SMEM = 26624 * 4;     // 106,496 B (2 blocks/SM)

    cudaFuncSetAttribute(k_fused, cudaFuncAttributeMaxDynamicSharedMemorySize, FUSED_SMEM);
    cudaFuncSetAttribute(k_augru, cudaFuncAttributeMaxDynamicSharedMemorySize, AUGRU_SMEM);

    k_sort<<<1, 512>>>(slen);
    k_prepw<<<96, 256>>>(Wu, Wr, Wc);
    k_fused<<<512, 256, FUSED_SMEM>>>(x, q, slen, W1, a1, W2, a2, W3);
    k_augru<<<B / 16, 256, AUGRU_SMEM>>>(slen, Wu, Wr, Wc, out);
}